// round 10
// baseline (speedup 1.0000x reference)
#include <cuda_runtime.h>
#include <cuda_fp16.h>
#include <mma.h>

using namespace nvcuda;

#define NN 50000
#define NE 800000
#define FF 128
#define MQ 32                      // uint2 (4 halves) per fp16 row
#define NG 64
#define NC 16

// GEMM tiling
#define BM 128
#define LDA 40                     // 32 + 8 skew
#define LDW 136                    // 128 + 8 skew
#define SMEM_FLOATS (BM * LDA + 32 * LDW)

// ---------------- scratch (static device globals; no allocation) ----------------
__device__ int    g_is64;
__device__ int    g_counts[NN];
__device__ int    g_fill[NN];      // absolute write cursor (init to rowptr)
__device__ int    g_rowptr[NN + 1];
__device__ int    g_col[NE];
__device__ float  g_dinv[NN];
__device__ uint2  g_msg[NN * MQ];    // fp16 messages (dinv-scaled GEMM output)
__device__ uint2  g_act[NN * MQ];    // fp16 activations (agg output, layer input)
__device__ float  g_pool[NG * FF];

// bit reinterpretation helpers
__device__ __forceinline__ unsigned h2u(__half2 h) { return *reinterpret_cast<unsigned*>(&h); }
__device__ __forceinline__ __half2 u2h(unsigned u) { return *reinterpret_cast<__half2*>(&u); }

// dtype-agnostic index load (edge_index / batch may be int32 or int64)
__device__ __forceinline__ int load_idx(const void* p, long long i, int is64) {
    if (is64) return (int)((const long long*)p)[i];
    return ((const int*)p)[i];
}

// ---------------- init: zero counts + dtype detect ----------------
__global__ void k_init(const int* __restrict__ w32) {
    int i = blockIdx.x * blockDim.x + threadIdx.x;
    if (i < NN) g_counts[i] = 0;
    if (i == 0) {
        int nz = 0;
        #pragma unroll
        for (int k = 0; k < 16; k++) nz |= w32[2 * k + 1];
        g_is64 = (nz == 0) ? 1 : 0;
    }
}

__global__ void k_count(const void* __restrict__ ei) {
    int i = blockIdx.x * blockDim.x + threadIdx.x;
    if (i >= NE) return;
    int d = load_idx(ei, (long long)NE + i, g_is64);
    atomicAdd(&g_counts[d], 1);
}

// single-block exclusive scan over 50000 counts -> rowptr, cursor, dinv
#define SCAN_T 1024
#define SCAN_CH 49                 // 1024*49 = 50176 >= NN
__global__ void __launch_bounds__(SCAN_T) k_scan() {
    __shared__ int wsum[32];
    int t = threadIdx.x;
    int lane = t & 31, wd = t >> 5;
    int start = t * SCAN_CH;
    int end = start + SCAN_CH; if (end > NN) end = NN;

    int local = 0;
    for (int i = start; i < end; i++) local += g_counts[i];

    int x = local;
    #pragma unroll
    for (int off = 1; off < 32; off <<= 1) {
        int tm = __shfl_up_sync(0xffffffffu, x, off);
        if (lane >= off) x += tm;
    }
    if (lane == 31) wsum[wd] = x;
    __syncthreads();
    if (wd == 0) {
        int w = wsum[lane];
        #pragma unroll
        for (int off = 1; off < 32; off <<= 1) {
            int tm = __shfl_up_sync(0xffffffffu, w, off);
            if (lane >= off) w += tm;
        }
        wsum[lane] = w;
    }
    __syncthreads();
    int run = (wd > 0 ? wsum[wd - 1] : 0) + x - local;   // exclusive prefix

    for (int i = start; i < end; i++) {
        int c = g_counts[i];
        g_rowptr[i] = run;
        g_fill[i]   = run;                                // cursor
        g_dinv[i]   = rsqrtf((float)(c + 1));             // +1 = self loop
        run += c;
    }
    if (t == 0) g_rowptr[NN] = NE;
}

__global__ void k_fill(const void* __restrict__ ei) {
    int i = blockIdx.x * blockDim.x + threadIdx.x;
    if (i >= NE) return;
    int is64 = g_is64;
    int s = load_idx(ei, (long long)i, is64);
    int d = load_idx(ei, (long long)NE + i, is64);
    int pos = atomicAdd(&g_fill[d], 1);                   // absolute cursor
    g_col[pos] = s;
}

// ---------------- GEMM (tf32): g_msg[r] = fp16( (src[r] @ W) * dinv[r] ) ----------------
// BM=128 rows/block, 128 cols, 8 warps. Warp: 32 rows (2 frag rows) x 64 cols (4 frag cols).
__global__ void __launch_bounds__(256) k_gemm(const float* __restrict__ xext,
                                              int srcSel,
                                              const float* __restrict__ W) {
    __shared__ float sm[SMEM_FLOATS];
    float* As = sm;               // 128 x LDA
    float* Ws = sm + BM * LDA;    // 32 x LDW

    const bool useX = (srcSel == 0);
    int tid = threadIdx.x;
    int wid = tid >> 5;
    int stripe = wid >> 1;        // 0..3 -> rows [stripe*32, +32)
    int half   = wid & 1;         // 0..1 -> cols [half*64, +64)
    int rowBase = blockIdx.x * BM;

    wmma::fragment<wmma::accumulator, 16, 16, 8, float> acc[2][4];
    #pragma unroll
    for (int r = 0; r < 2; r++)
        #pragma unroll
        for (int c = 0; c < 4; c++) wmma::fill_fragment(acc[r][c], 0.0f);

    for (int kc = 0; kc < 4; kc++) {              // K chunks of 32
        #pragma unroll
        for (int t = 0; t < 4; t++) {
            int idx = tid + t * 256;
            int r   = idx >> 3;
            int kq  = idx & 7;
            int grow = rowBase + r;
            float4 v = make_float4(0.f, 0.f, 0.f, 0.f);
            if (grow < NN) {
                if (useX) {
                    v = *(const float4*)&xext[(long long)grow * FF + kc * 32 + kq * 4];
                } else {
                    uint2 u = g_act[grow * MQ + kc * 8 + kq];
                    float2 lo = __half22float2(u2h(u.x));
                    float2 hi = __half22float2(u2h(u.y));
                    v = make_float4(lo.x, lo.y, hi.x, hi.y);
                }
            }
            float* dst = &As[r * LDA + kq * 4];
            dst[0] = wmma::__float_to_tf32(v.x);
            dst[1] = wmma::__float_to_tf32(v.y);
            dst[2] = wmma::__float_to_tf32(v.z);
            dst[3] = wmma::__float_to_tf32(v.w);
        }
        #pragma unroll
        for (int t = 0; t < 4; t++) {
            int idx = tid + t * 256;
            int k   = idx >> 5;
            int cq  = idx & 31;
            float4 v = *(const float4*)&W[(kc * 32 + k) * FF + cq * 4];
            float* dst = &Ws[k * LDW + cq * 4];
            dst[0] = wmma::__float_to_tf32(v.x);
            dst[1] = wmma::__float_to_tf32(v.y);
            dst[2] = wmma::__float_to_tf32(v.z);
            dst[3] = wmma::__float_to_tf32(v.w);
        }
        __syncthreads();

        #pragma unroll
        for (int kk = 0; kk < 4; kk++) {
            wmma::fragment<wmma::matrix_a, 16, 16, 8, wmma::precision::tf32, wmma::row_major> a0, a1;
            wmma::load_matrix_sync(a0, &As[(stripe * 32) * LDA + kk * 8], LDA);
            wmma::load_matrix_sync(a1, &As[(stripe * 32 + 16) * LDA + kk * 8], LDA);
            #pragma unroll
            for (int c = 0; c < 4; c++) {
                wmma::fragment<wmma::matrix_b, 16, 16, 8, wmma::precision::tf32, wmma::row_major> b;
                wmma::load_matrix_sync(b, &Ws[kk * 8 * LDW + half * 64 + c * 16], LDW);
                wmma::mma_sync(acc[0][c], a0, b, acc[0][c]);
                wmma::mma_sync(acc[1][c], a1, b, acc[1][c]);
            }
        }
        __syncthreads();
    }

    // epilogue in two 64-row passes through shared (Cs = 64 x LDW, reuses sm)
    float* Cs = sm;
    #pragma unroll
    for (int pass = 0; pass < 2; pass++) {
        if ((stripe >> 1) == pass) {
            int localStripe = stripe & 1;
            #pragma unroll
            for (int rt = 0; rt < 2; rt++)
                #pragma unroll
                for (int c = 0; c < 4; c++)
                    wmma::store_matrix_sync(&Cs[(localStripe * 32 + rt * 16) * LDW + half * 64 + c * 16],
                                            acc[rt][c], LDW, wmma::mem_row_major);
        }
        __syncthreads();
        #pragma unroll
        for (int t = 0; t < 8; t++) {
            int idx = tid + t * 256;
            int r = idx >> 5;
            int q = idx & 31;
            int grow = rowBase + pass * 64 + r;
            if (grow < NN) {
                float dv = g_dinv[grow];
                float4 v = *(float4*)&Cs[r * LDW + q * 4];
                __half2 h0 = __floats2half2_rn(v.x * dv, v.y * dv);
                __half2 h1 = __floats2half2_rn(v.z * dv, v.w * dv);
                uint2 u;
                u.x = h2u(h0);
                u.y = h2u(h1);
                g_msg[grow * MQ + q] = u;
            }
        }
        __syncthreads();
    }
}

// ---------------- aggregation: act[v] = fp16( relu?( dinv[v]*sum msg + b ) ) ----
__global__ void __launch_bounds__(256) k_agg(const float* __restrict__ bias,
                                             int do_relu) {
    int v    = (blockIdx.x * blockDim.x + threadIdx.x) >> 5;  // one warp per node
    int lane = threadIdx.x & 31;
    if (v >= NN) return;

    uint2 mself = g_msg[(v << 5) + lane];
    __half2 c0a = u2h(mself.x), c0b = u2h(mself.y);
    __half2 z = __floats2half2_rn(0.f, 0.f);
    __half2 c1a = z, c1b = z, c2a = z, c2b = z, c3a = z, c3b = z;

    int s = g_rowptr[v];
    int deg = g_rowptr[v + 1] - s;

    for (int base = 0; base < deg; base += 32) {
        int rem = deg - base;
        int n = rem < 32 ? rem : 32;
        int myc = 0;
        if (lane < n) myc = g_col[s + base + lane];            // coalesced prefetch

        int jj = 0;
        for (; jj + 8 <= n; jj += 8) {
            int u0 = __shfl_sync(0xffffffffu, myc, jj);
            int u1 = __shfl_sync(0xffffffffu, myc, jj + 1);
            int u2 = __shfl_sync(0xffffffffu, myc, jj + 2);
            int u3 = __shfl_sync(0xffffffffu, myc, jj + 3);
            int u4 = __shfl_sync(0xffffffffu, myc, jj + 4);
            int u5 = __shfl_sync(0xffffffffu, myc, jj + 5);
            int u6 = __shfl_sync(0xffffffffu, myc, jj + 6);
            int u7 = __shfl_sync(0xffffffffu, myc, jj + 7);
            uint2 m0 = g_msg[(u0 << 5) + lane];
            uint2 m1 = g_msg[(u1 << 5) + lane];
            uint2 m2 = g_msg[(u2 << 5) + lane];
            uint2 m3 = g_msg[(u3 << 5) + lane];
            uint2 m4 = g_msg[(u4 << 5) + lane];
            uint2 m5 = g_msg[(u5 << 5) + lane];
            uint2 m6 = g_msg[(u6 << 5) + lane];
            uint2 m7 = g_msg[(u7 << 5) + lane];
            c0a = __hadd2(c0a, u2h(m0.x)); c0b = __hadd2(c0b, u2h(m0.y));
            c1a = __hadd2(c1a, u2h(m1.x)); c1b = __hadd2(c1b, u2h(m1.y));
            c2a = __hadd2(c2a, u2h(m2.x)); c2b = __hadd2(c2b, u2h(m2.y));
            c3a = __hadd2(c3a, u2h(m3.x)); c3b = __hadd2(c3b, u2h(m3.y));
            c0a = __hadd2(c0a, u2h(m4.x)); c0b = __hadd2(c0b, u2h(m4.y));
            c1a = __hadd2(c1a, u2h(m5.x)); c1b = __hadd2(c1b, u2h(m5.y));
            c2a = __hadd2(c2a, u2h(m6.x)); c2b = __hadd2(c2b, u2h(m6.y));
            c3a = __hadd2(c3a, u2h(m7.x)); c3b = __hadd2(c3b, u2h(m7.y));
        }
        for (; jj + 2 <= n; jj += 2) {
            int u0 = __shfl_sync(0xffffffffu, myc, jj);
            int u1 = __shfl_sync(0xffffffffu, myc, jj + 1);
            uint2 m0 = g_msg[(u0 << 5) + lane];
            uint2 m1 = g_msg[(u1 << 5) + lane];
            c0a = __hadd2(c0a, u2h(m0.x)); c0b = __hadd2(c0b, u2h(m0.y));
            c1a = __hadd2(c1a, u2h(m1.x)); c1b = __hadd2(c1b, u2h(m1.y));
        }
        if (jj < n) {
            int u = __shfl_sync(0xffffffffu, myc, jj);
            uint2 m = g_msg[(u << 5) + lane];
            c2a = __hadd2(c2a, u2h(m.x)); c2b = __hadd2(c2b, u2h(m.y));
        }
    }

    float2 f0a = __half22float2(c0a), f1a = __half22float2(c1a);
    float2 f2a = __half22float2(c2a), f3a = __half22float2(c3a);
    float2 f0b = __half22float2(c0b), f1b = __half22float2(c1b);
    float2 f2b = __half22float2(c2b), f3b = __half22float2(c3b);

    float  dv = g_dinv[v];
    float4 b  = *(const float4*)&bias[lane * 4];
    float4 acc;
    acc.x = (f0a.x + f1a.x + f2a.x + f3a.x) * dv + b.x;
    acc.y = (f0a.y + f1a.y + f2a.y + f3a.y) * dv + b.y;
    acc.z = (f0b.x + f1b.x + f2b.x + f3b.x) * dv + b.z;
    acc.w = (f0b.y + f1b.y + f2b.y + f3b.y) * dv + b.w;
    if (do_relu) {
        acc.x = fmaxf(acc.x, 0.f); acc.y = fmaxf(acc.y, 0.f);
        acc.z = fmaxf(acc.z, 0.f); acc.w = fmaxf(acc.w, 0.f);
    }
    __half2 h0 = __floats2half2_rn(acc.x, acc.y);
    __half2 h1 = __floats2half2_rn(acc.z, acc.w);
    uint2 u;
    u.x = h2u(h0);
    u.y = h2u(h1);
    g_act[(v << 5) + lane] = u;
}

// ---------------- mean pooling per graph (batch sorted); reads fp16 g_act ----------------
__device__ __forceinline__ int lower_bound_idx(const void* a, int val, int is64) {
    int lo = 0, hi = NN;
    while (lo < hi) {
        int mid = (lo + hi) >> 1;
        if (load_idx(a, mid, is64) < val) lo = mid + 1; else hi = mid;
    }
    return lo;
}

__global__ void __launch_bounds__(1024) k_pool(const void* __restrict__ batch) {
    __shared__ int se[2];
    __shared__ float red[8][FF];
    int g = blockIdx.x;
    if (threadIdx.x == 0) {
        int is64 = g_is64;
        se[0] = lower_bound_idx(batch, g, is64);
        se[1] = lower_bound_idx(batch, g + 1, is64);
    }
    __syncthreads();
    int s = se[0], e = se[1];
    int col = threadIdx.x & 127;       // feature
    int rc  = threadIdx.x >> 7;        // 0..7 row chunk
    const __half* h = (const __half*)g_act;
    float sum = 0.f;
    for (int i = s + rc; i < e; i += 8) sum += __half2float(h[i * FF + col]);
    red[rc][col] = sum;
    __syncthreads();
    if (rc == 0) {
        float t = 0.f;
        #pragma unroll
        for (int k = 0; k < 8; k++) t += red[k][col];
        float cnt = (float)(e - s);
        g_pool[g * FF + col] = t / fmaxf(cnt, 1.0f);
    }
}

// ---------------- classifier ----------------
__global__ void k_cls(const float* __restrict__ Wc,
                      const float* __restrict__ bc,
                      float* __restrict__ out) {
    int tid = threadIdx.x;             // 1024 threads
    int g = tid >> 4;
    int c = tid & 15;
    float sum = bc[c];
    #pragma unroll 8
    for (int k = 0; k < FF; k++)
        sum += g_pool[g * FF + k] * Wc[k * NC + c];
    out[g * NC + c] = sum;
}

// ---------------- launch ----------------
extern "C" void kernel_launch(void* const* d_in, const int* in_sizes, int n_in,
                              void* d_out, int out_size) {
    const float* x  = (const float*)d_in[0];
    const void*  ei = d_in[1];
    const void*  batch = d_in[2];
    const float* W0 = (const float*)d_in[3];
    const float* b0 = (const float*)d_in[4];
    const float* W1 = (const float*)d_in[5];
    const float* b1 = (const float*)d_in[6];
    const float* W2 = (const float*)d_in[7];
    const float* b2 = (const float*)d_in[8];
    const float* Wc = (const float*)d_in[9];
    const float* bc = (const float*)d_in[10];
    float* out = (float*)d_out;

    const int gemm_grid = (NN + BM - 1) / BM;
    const int agg_grid  = (NN + 7) / 8;

    k_init <<<(NN + 255) / 256, 256>>>((const int*)ei);   // launch 1
    k_count<<<(NE + 255) / 256, 256>>>(ei);               // launch 2
    k_scan <<<1, SCAN_T>>>();                             // launch 3 (rowptr+cursor+dinv)
    k_gemm <<<gemm_grid, 256>>>(x, 0, W0);                // launch 4 (profiled)
    k_fill <<<(NE + 255) / 256, 256>>>(ei);               // launch 5
    k_agg  <<<agg_grid,  256>>>(b0, 1);                   // launch 6
    k_gemm <<<gemm_grid, 256>>>(x, 1, W1);
    k_agg  <<<agg_grid,  256>>>(b1, 1);
    k_gemm <<<gemm_grid, 256>>>(x, 1, W2);
    k_agg  <<<agg_grid,  256>>>(b2, 0);

    k_pool<<<NG, 1024>>>(batch);
    k_cls <<<1, 1024>>>(Wc, bc, out);
}

// round 11
// speedup vs baseline: 1.9304x; 1.9304x over previous
#include <cuda_runtime.h>
#include <cuda_fp16.h>
#include <mma.h>

using namespace nvcuda;

#define NN 50000
#define NE 800000
#define FF 128
#define MQ 32                      // uint2 (4 halves) per fp16 row
#define NG 64
#define NC 16
#define SCAN_B 512
#define NBLK ((NN + SCAN_B - 1) / SCAN_B)   // 98

// GEMM tiling (fp16 HMMA)
#define BM 128
#define BK 64
#define ASTR 72                    // A smem stride in halves (64 + 8 skew)
#define WSTR 136                   // W smem stride in halves (128 + 8 skew)
#define SMEM_BYTES 35840           // As 128*72*2 + Ws 64*136*2; Cs (64*136*4=34816) reuses

// ---------------- scratch (static device globals; no allocation) ----------------
__device__ int    g_is64;
__device__ int    g_counts[NN];
__device__ int    g_fill[NN];      // absolute write cursor (set to rowptr in scan3)
__device__ int    g_rowptr[NN + 1];
__device__ int    g_col[NE];
__device__ float  g_dinv[NN];
__device__ __half g_Wh[3][FF * FF];  // fp16 weights (converted in k_init)
__device__ uint2  g_msg[NN * MQ];    // fp16 messages (dinv-scaled GEMM output)
__device__ uint2  g_act[NN * MQ];    // fp16 activations (agg output, layer input)
__device__ float  g_pool[NG * FF];
__device__ int    g_bsum[NBLK];

// bit reinterpretation helpers
__device__ __forceinline__ unsigned h2u(__half2 h) { return *reinterpret_cast<unsigned*>(&h); }
__device__ __forceinline__ __half2 u2h(unsigned u) { return *reinterpret_cast<__half2*>(&u); }

// dtype-agnostic index load (edge_index / batch may be int32 or int64)
__device__ __forceinline__ int load_idx(const void* p, long long i, int is64) {
    if (is64) return (int)((const long long*)p)[i];
    return ((const int*)p)[i];
}

// ---------------- init: zero counts + dtype detect + W fp16 conversion ----------------
__global__ void k_init(const int* __restrict__ w32,
                       const float* __restrict__ W0,
                       const float* __restrict__ W1,
                       const float* __restrict__ W2) {
    int i = blockIdx.x * blockDim.x + threadIdx.x;
    if (i < NN) g_counts[i] = 0;
    if (i < FF * FF) {
        g_Wh[0][i] = __float2half_rn(W0[i]);
        g_Wh[1][i] = __float2half_rn(W1[i]);
        g_Wh[2][i] = __float2half_rn(W2[i]);
    }
    if (i == 0) {
        int nz = 0;
        #pragma unroll
        for (int k = 0; k < 16; k++) nz |= w32[2 * k + 1];
        g_is64 = (nz == 0) ? 1 : 0;
    }
}

__global__ void k_count(const void* __restrict__ ei) {
    int i = blockIdx.x * blockDim.x + threadIdx.x;
    if (i >= NE) return;
    int d = load_idx(ei, (long long)NE + i, g_is64);
    atomicAdd(&g_counts[d], 1);
}

// block-wide inclusive scan via shuffles; writes exclusive partials + block sums
__global__ void k_scan1() {
    __shared__ int warp_sums[SCAN_B / 32];
    int i = blockIdx.x * SCAN_B + threadIdx.x;
    int v = (i < NN) ? g_counts[i] : 0;
    int lane = threadIdx.x & 31;
    int wid  = threadIdx.x >> 5;

    int x = v;
    #pragma unroll
    for (int off = 1; off < 32; off <<= 1) {
        int t = __shfl_up_sync(0xffffffffu, x, off);
        if (lane >= off) x += t;
    }
    if (lane == 31) warp_sums[wid] = x;
    __syncthreads();
    if (wid == 0) {
        int w = (lane < SCAN_B / 32) ? warp_sums[lane] : 0;
        #pragma unroll
        for (int off = 1; off < SCAN_B / 32; off <<= 1) {
            int t = __shfl_up_sync(0xffffffffu, w, off);
            if (lane >= off) w += t;
        }
        if (lane < SCAN_B / 32) warp_sums[lane] = w;
    }
    __syncthreads();
    int base = (wid > 0) ? warp_sums[wid - 1] : 0;
    int incl = base + x;
    if (i < NN) g_rowptr[i] = incl - v;            // exclusive within block
    if (threadIdx.x == SCAN_B - 1) g_bsum[blockIdx.x] = incl;
}

// finalize rowptr: block b adds sum(bsum[0..b-1]); also cursor + dinv
__global__ void k_scan3() {
    __shared__ int s_off;
    int b = blockIdx.x;
    if (threadIdx.x < 32) {
        int acc = 0;
        for (int k = threadIdx.x; k < b; k += 32) acc += g_bsum[k];
        #pragma unroll
        for (int off = 16; off; off >>= 1) acc += __shfl_down_sync(0xffffffffu, acc, off);
        if (threadIdx.x == 0) s_off = acc;
    }
    __syncthreads();
    int i = b * SCAN_B + threadIdx.x;
    if (i < NN) {
        int rp = g_rowptr[i] + s_off;
        g_rowptr[i] = rp;
        g_fill[i]   = rp;                               // absolute cursor
        g_dinv[i]   = rsqrtf((float)(g_counts[i] + 1)); // +1 = self loop
    }
    if (i == 0) g_rowptr[NN] = NE;
}

__global__ void k_fill(const void* __restrict__ ei) {
    int i = blockIdx.x * blockDim.x + threadIdx.x;
    if (i >= NE) return;
    int is64 = g_is64;
    int s = load_idx(ei, (long long)i, is64);
    int d = load_idx(ei, (long long)NE + i, is64);
    int pos = atomicAdd(&g_fill[d], 1);
    g_col[pos] = s;
}

// ---------------- GEMM (fp16 HMMA): g_msg[r] = fp16( (src[r] @ W) * dinv[r] ) ----------------
// BM=128 rows/block, 128 cols, BK=64, 8 warps. Warp: 32 rows x 64 cols via 2x4 m16n16k16 frags.
__global__ void __launch_bounds__(256) k_gemm(const float* __restrict__ xext,
                                              int srcSel,
                                              int wSel) {
    __shared__ __align__(16) char smraw[SMEM_BYTES];
    __half* As = (__half*)smraw;                  // 128 x ASTR
    __half* Ws = (__half*)smraw + BM * ASTR;      // 64 x WSTR
    float*  Cs = (float*)smraw;                   // 64 x WSTR (epilogue reuse)

    const bool useX = (srcSel == 0);
    const __half* Wh = g_Wh[wSel];
    int tid = threadIdx.x;
    int wid = tid >> 5;
    int stripe = wid >> 1;        // 0..3 -> rows [stripe*32, +32)
    int half_  = wid & 1;         // 0..1 -> cols [half_*64, +64)
    int rowBase = blockIdx.x * BM;

    wmma::fragment<wmma::accumulator, 16, 16, 16, float> acc[2][4];
    #pragma unroll
    for (int r = 0; r < 2; r++)
        #pragma unroll
        for (int c = 0; c < 4; c++) wmma::fill_fragment(acc[r][c], 0.0f);

    for (int kc = 0; kc < 2; kc++) {              // K chunks of 64
        // A tile: 128 rows x 64 halves. 128x16 quads (4 halves) = 2048, 8 per thread.
        #pragma unroll
        for (int t = 0; t < 8; t++) {
            int idx = tid + t * 256;
            int r   = idx >> 4;
            int kq  = idx & 15;                   // quad of 4 halves
            int grow = rowBase + r;
            uint2 u = make_uint2(0u, 0u);
            if (grow < NN) {
                if (useX) {
                    float4 v = *(const float4*)&xext[(long long)grow * FF + kc * 64 + kq * 4];
                    u.x = h2u(__floats2half2_rn(v.x, v.y));
                    u.y = h2u(__floats2half2_rn(v.z, v.w));
                } else {
                    u = g_act[grow * MQ + kc * 16 + kq];
                }
            }
            *(uint2*)&As[r * ASTR + kq * 4] = u;
        }
        // W chunk: 64 rows x 128 halves = 64x16 octs (8 halves) = 1024 uint4, 4 per thread.
        #pragma unroll
        for (int t = 0; t < 4; t++) {
            int idx = tid + t * 256;
            int k   = idx >> 4;
            int co  = idx & 15;                   // oct of 8 halves
            uint4 v = *(const uint4*)&Wh[(kc * 64 + k) * FF + co * 8];
            *(uint4*)&Ws[k * WSTR + co * 8] = v;
        }
        __syncthreads();

        #pragma unroll
        for (int kk = 0; kk < 4; kk++) {          // K steps of 16
            wmma::fragment<wmma::matrix_a, 16, 16, 16, __half, wmma::row_major> a0, a1;
            wmma::load_matrix_sync(a0, &As[(stripe * 32) * ASTR + kk * 16], ASTR);
            wmma::load_matrix_sync(a1, &As[(stripe * 32 + 16) * ASTR + kk * 16], ASTR);
            #pragma unroll
            for (int c = 0; c < 4; c++) {
                wmma::fragment<wmma::matrix_b, 16, 16, 16, __half, wmma::row_major> b;
                wmma::load_matrix_sync(b, &Ws[(kk * 16) * WSTR + half_ * 64 + c * 16], WSTR);
                wmma::mma_sync(acc[0][c], a0, b, acc[0][c]);
                wmma::mma_sync(acc[1][c], a1, b, acc[1][c]);
            }
        }
        __syncthreads();
    }

    // epilogue in two 64-row passes through shared (Cs = 64 x WSTR floats)
    #pragma unroll
    for (int pass = 0; pass < 2; pass++) {
        if ((stripe >> 1) == pass) {
            int localStripe = stripe & 1;
            #pragma unroll
            for (int rt = 0; rt < 2; rt++)
                #pragma unroll
                for (int c = 0; c < 4; c++)
                    wmma::store_matrix_sync(&Cs[(localStripe * 32 + rt * 16) * WSTR + half_ * 64 + c * 16],
                                            acc[rt][c], WSTR, wmma::mem_row_major);
        }
        __syncthreads();
        #pragma unroll
        for (int t = 0; t < 8; t++) {
            int idx = tid + t * 256;               // 64 rows x 32 quads
            int r = idx >> 5;
            int q = idx & 31;
            int grow = rowBase + pass * 64 + r;
            if (grow < NN) {
                float dv = g_dinv[grow];
                float4 v = *(float4*)&Cs[r * WSTR + q * 4];
                uint2 u;
                u.x = h2u(__floats2half2_rn(v.x * dv, v.y * dv));
                u.y = h2u(__floats2half2_rn(v.z * dv, v.w * dv));
                g_msg[grow * MQ + q] = u;
            }
        }
        __syncthreads();
    }
}

// ---------------- aggregation: act[v] = fp16( relu?( dinv[v]*sum msg + b ) ) ----
__global__ void __launch_bounds__(256) k_agg(const float* __restrict__ bias,
                                             int do_relu) {
    int v    = (blockIdx.x * blockDim.x + threadIdx.x) >> 5;  // one warp per node
    int lane = threadIdx.x & 31;
    if (v >= NN) return;

    uint2 mself = g_msg[(v << 5) + lane];
    __half2 c0a = u2h(mself.x), c0b = u2h(mself.y);
    __half2 z = __floats2half2_rn(0.f, 0.f);
    __half2 c1a = z, c1b = z, c2a = z, c2b = z, c3a = z, c3b = z;

    int s = g_rowptr[v];
    int deg = g_rowptr[v + 1] - s;

    for (int base = 0; base < deg; base += 32) {
        int rem = deg - base;
        int n = rem < 32 ? rem : 32;
        int myc = 0;
        if (lane < n) myc = g_col[s + base + lane];            // coalesced prefetch

        int jj = 0;
        for (; jj + 8 <= n; jj += 8) {
            int u0 = __shfl_sync(0xffffffffu, myc, jj);
            int u1 = __shfl_sync(0xffffffffu, myc, jj + 1);
            int u2 = __shfl_sync(0xffffffffu, myc, jj + 2);
            int u3 = __shfl_sync(0xffffffffu, myc, jj + 3);
            int u4 = __shfl_sync(0xffffffffu, myc, jj + 4);
            int u5 = __shfl_sync(0xffffffffu, myc, jj + 5);
            int u6 = __shfl_sync(0xffffffffu, myc, jj + 6);
            int u7 = __shfl_sync(0xffffffffu, myc, jj + 7);
            uint2 m0 = g_msg[(u0 << 5) + lane];
            uint2 m1 = g_msg[(u1 << 5) + lane];
            uint2 m2 = g_msg[(u2 << 5) + lane];
            uint2 m3 = g_msg[(u3 << 5) + lane];
            uint2 m4 = g_msg[(u4 << 5) + lane];
            uint2 m5 = g_msg[(u5 << 5) + lane];
            uint2 m6 = g_msg[(u6 << 5) + lane];
            uint2 m7 = g_msg[(u7 << 5) + lane];
            c0a = __hadd2(c0a, u2h(m0.x)); c0b = __hadd2(c0b, u2h(m0.y));
            c1a = __hadd2(c1a, u2h(m1.x)); c1b = __hadd2(c1b, u2h(m1.y));
            c2a = __hadd2(c2a, u2h(m2.x)); c2b = __hadd2(c2b, u2h(m2.y));
            c3a = __hadd2(c3a, u2h(m3.x)); c3b = __hadd2(c3b, u2h(m3.y));
            c0a = __hadd2(c0a, u2h(m4.x)); c0b = __hadd2(c0b, u2h(m4.y));
            c1a = __hadd2(c1a, u2h(m5.x)); c1b = __hadd2(c1b, u2h(m5.y));
            c2a = __hadd2(c2a, u2h(m6.x)); c2b = __hadd2(c2b, u2h(m6.y));
            c3a = __hadd2(c3a, u2h(m7.x)); c3b = __hadd2(c3b, u2h(m7.y));
        }
        for (; jj + 2 <= n; jj += 2) {
            int u0 = __shfl_sync(0xffffffffu, myc, jj);
            int u1 = __shfl_sync(0xffffffffu, myc, jj + 1);
            uint2 m0 = g_msg[(u0 << 5) + lane];
            uint2 m1 = g_msg[(u1 << 5) + lane];
            c0a = __hadd2(c0a, u2h(m0.x)); c0b = __hadd2(c0b, u2h(m0.y));
            c1a = __hadd2(c1a, u2h(m1.x)); c1b = __hadd2(c1b, u2h(m1.y));
        }
        if (jj < n) {
            int u = __shfl_sync(0xffffffffu, myc, jj);
            uint2 m = g_msg[(u << 5) + lane];
            c2a = __hadd2(c2a, u2h(m.x)); c2b = __hadd2(c2b, u2h(m.y));
        }
    }

    float2 f0a = __half22float2(c0a), f1a = __half22float2(c1a);
    float2 f2a = __half22float2(c2a), f3a = __half22float2(c3a);
    float2 f0b = __half22float2(c0b), f1b = __half22float2(c1b);
    float2 f2b = __half22float2(c2b), f3b = __half22float2(c3b);

    float  dv = g_dinv[v];
    float4 b  = *(const float4*)&bias[lane * 4];
    float4 acc;
    acc.x = (f0a.x + f1a.x + f2a.x + f3a.x) * dv + b.x;
    acc.y = (f0a.y + f1a.y + f2a.y + f3a.y) * dv + b.y;
    acc.z = (f0b.x + f1b.x + f2b.x + f3b.x) * dv + b.z;
    acc.w = (f0b.y + f1b.y + f2b.y + f3b.y) * dv + b.w;
    if (do_relu) {
        acc.x = fmaxf(acc.x, 0.f); acc.y = fmaxf(acc.y, 0.f);
        acc.z = fmaxf(acc.z, 0.f); acc.w = fmaxf(acc.w, 0.f);
    }
    uint2 u;
    u.x = h2u(__floats2half2_rn(acc.x, acc.y));
    u.y = h2u(__floats2half2_rn(acc.z, acc.w));
    g_act[(v << 5) + lane] = u;
}

// ---------------- mean pooling per graph (batch sorted); reads fp16 g_act ----------------
__device__ __forceinline__ int lower_bound_idx(const void* a, int val, int is64) {
    int lo = 0, hi = NN;
    while (lo < hi) {
        int mid = (lo + hi) >> 1;
        if (load_idx(a, mid, is64) < val) lo = mid + 1; else hi = mid;
    }
    return lo;
}

__global__ void __launch_bounds__(1024) k_pool(const void* __restrict__ batch) {
    __shared__ int se[2];
    __shared__ float red[8][FF];
    int g = blockIdx.x;
    if (threadIdx.x == 0) {
        int is64 = g_is64;
        se[0] = lower_bound_idx(batch, g, is64);
        se[1] = lower_bound_idx(batch, g + 1, is64);
    }
    __syncthreads();
    int s = se[0], e = se[1];
    int col = threadIdx.x & 127;
    int rc  = threadIdx.x >> 7;
    const __half* h = (const __half*)g_act;
    float sum = 0.f;
    for (int i = s + rc; i < e; i += 8) sum += __half2float(h[i * FF + col]);
    red[rc][col] = sum;
    __syncthreads();
    if (rc == 0) {
        float t = 0.f;
        #pragma unroll
        for (int k = 0; k < 8; k++) t += red[k][col];
        float cnt = (float)(e - s);
        g_pool[g * FF + col] = t / fmaxf(cnt, 1.0f);
    }
}

// ---------------- classifier ----------------
__global__ void k_cls(const float* __restrict__ Wc,
                      const float* __restrict__ bc,
                      float* __restrict__ out) {
    int tid = threadIdx.x;
    int g = tid >> 4;
    int c = tid & 15;
    float sum = bc[c];
    #pragma unroll 8
    for (int k = 0; k < FF; k++)
        sum += g_pool[g * FF + k] * Wc[k * NC + c];
    out[g * NC + c] = sum;
}

// ---------------- launch ----------------
extern "C" void kernel_launch(void* const* d_in, const int* in_sizes, int n_in,
                              void* d_out, int out_size) {
    const float* x  = (const float*)d_in[0];
    const void*  ei = d_in[1];
    const void*  batch = d_in[2];
    const float* W0 = (const float*)d_in[3];
    const float* b0 = (const float*)d_in[4];
    const float* W1 = (const float*)d_in[5];
    const float* b1 = (const float*)d_in[6];
    const float* W2 = (const float*)d_in[7];
    const float* b2 = (const float*)d_in[8];
    const float* Wc = (const float*)d_in[9];
    const float* bc = (const float*)d_in[10];
    float* out = (float*)d_out;

    const int gemm_grid = (NN + BM - 1) / BM;
    const int agg_grid  = (NN + 7) / 8;

    k_init <<<(NN + 255) / 256, 256>>>((const int*)ei, W0, W1, W2);
    k_count<<<(NE + 255) / 256, 256>>>(ei);
    k_scan1<<<NBLK, SCAN_B>>>();
    k_scan3<<<NBLK, SCAN_B>>>();
    k_fill <<<(NE + 255) / 256, 256>>>(ei);

    k_gemm<<<gemm_grid, 256>>>(x, 0, 0);
    k_agg <<<agg_grid,  256>>>(b0, 1);
    k_gemm<<<gemm_grid, 256>>>(x, 1, 1);
    k_agg <<<agg_grid,  256>>>(b1, 1);
    k_gemm<<<gemm_grid, 256>>>(x, 1, 2);
    k_agg <<<agg_grid,  256>>>(b2, 0);

    k_pool<<<NG, 1024>>>(batch);
    k_cls <<<1, 1024>>>(Wc, bc, out);
}

// round 13
// speedup vs baseline: 1.9727x; 1.0219x over previous
#include <cuda_runtime.h>
#include <cuda_fp16.h>
#include <mma.h>

using namespace nvcuda;

#define NN 50000
#define NE 800000
#define FF 128
#define MQ 32                      // uint2 (4 halves) per fp16 row
#define NG 64
#define NC 16
#define SCAN_B 512
#define NBLK ((NN + SCAN_B - 1) / SCAN_B)   // 98

// GEMM tiling (fp16 HMMA)
#define BM 128
#define BK 64
#define ASTR 72                    // A smem stride in halves (64 + 8 skew)
#define WSTR 136                   // W smem stride in halves (128 + 8 skew)
#define SMEM_BYTES 35840           // As 128*72*2 + Ws 64*136*2; Cs (64*136*4) reuses

// ---------------- scratch (static device globals; no allocation) ----------------
__device__ int      g_is64;
__device__ int      g_counts[NN];
__device__ int      g_fill[NN];      // absolute write cursor
__device__ int      g_rowptr[NN + 1];
__device__ int      g_col[NE];
__device__ float    g_dinv[NN];
__device__ __half   g_Wh[3][FF * FF];  // fp16 weights (converted in k_init)
__device__ uint2    g_msg[NN * MQ];    // fp16 messages (dinv-scaled GEMM output)
__device__ uint2    g_act[NN * MQ];    // fp16 activations (agg output, layer input)
__device__ volatile int g_sflag[NBLK]; // scan publish flags
__device__ volatile int g_sval[NBLK];  // scan block sums

// bit reinterpretation helpers
__device__ __forceinline__ unsigned h2u(__half2 h) { return *reinterpret_cast<unsigned*>(&h); }
__device__ __forceinline__ __half2 u2h(unsigned u) { return *reinterpret_cast<__half2*>(&u); }

// dtype-agnostic index load (edge_index / batch may be int32 or int64)
__device__ __forceinline__ int load_idx(const void* p, long long i, int is64) {
    if (is64) return (int)((const long long*)p)[i];
    return ((const int*)p)[i];
}

// ---------------- init: zero counts/flags + dtype detect + W fp16 conversion ----------------
__global__ void k_init(const int* __restrict__ w32,
                       const float* __restrict__ W0,
                       const float* __restrict__ W1,
                       const float* __restrict__ W2) {
    int i = blockIdx.x * blockDim.x + threadIdx.x;
    if (i < NN) g_counts[i] = 0;
    if (i < NBLK) g_sflag[i] = 0;
    if (i < FF * FF) {
        g_Wh[0][i] = __float2half_rn(W0[i]);
        g_Wh[1][i] = __float2half_rn(W1[i]);
        g_Wh[2][i] = __float2half_rn(W2[i]);
    }
    if (i == 0) {
        int nz = 0;
        #pragma unroll
        for (int k = 0; k < 16; k++) nz |= w32[2 * k + 1];
        g_is64 = (nz == 0) ? 1 : 0;
    }
}

__global__ void k_count(const void* __restrict__ ei) {
    int i = blockIdx.x * blockDim.x + threadIdx.x;
    if (i >= NE) return;
    int d = load_idx(ei, (long long)NE + i, g_is64);
    atomicAdd(&g_counts[d], 1);
}

// single-pass scan with decoupled lookback: rowptr, cursor, dinv in one kernel.
// 98 blocks (< #SMs, all resident) -> spin on predecessors is deadlock-free.
__global__ void __launch_bounds__(SCAN_B) k_scan() {
    __shared__ int warp_sums[SCAN_B / 32];
    __shared__ int s_off;
    int b = blockIdx.x;
    int i = b * SCAN_B + threadIdx.x;
    int v = (i < NN) ? g_counts[i] : 0;
    int lane = threadIdx.x & 31;
    int wid  = threadIdx.x >> 5;

    // block-local inclusive scan
    int x = v;
    #pragma unroll
    for (int off = 1; off < 32; off <<= 1) {
        int t = __shfl_up_sync(0xffffffffu, x, off);
        if (lane >= off) x += t;
    }
    if (lane == 31) warp_sums[wid] = x;
    __syncthreads();
    if (wid == 0) {
        int w = (lane < SCAN_B / 32) ? warp_sums[lane] : 0;
        #pragma unroll
        for (int off = 1; off < SCAN_B / 32; off <<= 1) {
            int t = __shfl_up_sync(0xffffffffu, w, off);
            if (lane >= off) w += t;
        }
        if (lane < SCAN_B / 32) warp_sums[lane] = w;
    }
    __syncthreads();
    int base = (wid > 0) ? warp_sums[wid - 1] : 0;
    int incl = base + x;

    // publish block total
    if (threadIdx.x == SCAN_B - 1) {
        g_sval[b] = incl;
        __threadfence();
        g_sflag[b] = 1;
    }

    // warp 0 gathers predecessor sums (spin until published)
    if (wid == 0) {
        int acc = 0;
        for (int k = lane; k < b; k += 32) {
            while (g_sflag[k] == 0) { }
            acc += g_sval[k];
        }
        #pragma unroll
        for (int off = 16; off; off >>= 1) acc += __shfl_down_sync(0xffffffffu, acc, off);
        if (lane == 0) s_off = acc;
    }
    __syncthreads();

    if (i < NN) {
        int rp = s_off + incl - v;                      // exclusive global prefix
        g_rowptr[i] = rp;
        g_fill[i]   = rp;                               // absolute cursor
        g_dinv[i]   = rsqrtf((float)(v + 1));           // +1 = self loop
    }
    if (i == 0) g_rowptr[NN] = NE;
}

__global__ void k_fill(const void* __restrict__ ei) {
    int i = blockIdx.x * blockDim.x + threadIdx.x;
    if (i >= NE) return;
    int is64 = g_is64;
    int s = load_idx(ei, (long long)i, is64);
    int d = load_idx(ei, (long long)NE + i, is64);
    int pos = atomicAdd(&g_fill[d], 1);
    g_col[pos] = s;
}

// ---------------- GEMM (fp16 HMMA): g_msg[r] = fp16( (src[r] @ W) * dinv[r] ) ----------------
__global__ void __launch_bounds__(256) k_gemm(const float* __restrict__ xext,
                                              int srcSel,
                                              int wSel) {
    __shared__ __align__(16) char smraw[SMEM_BYTES];
    __half* As = (__half*)smraw;                  // 128 x ASTR
    __half* Ws = (__half*)smraw + BM * ASTR;      // 64 x WSTR
    float*  Cs = (float*)smraw;                   // 64 x WSTR (epilogue reuse)

    const bool useX = (srcSel == 0);
    const __half* Wh = g_Wh[wSel];
    int tid = threadIdx.x;
    int wid = tid >> 5;
    int stripe = wid >> 1;        // 0..3 -> rows [stripe*32, +32)
    int half_  = wid & 1;         // 0..1 -> cols [half_*64, +64)
    int rowBase = blockIdx.x * BM;

    wmma::fragment<wmma::accumulator, 16, 16, 16, float> acc[2][4];
    #pragma unroll
    for (int r = 0; r < 2; r++)
        #pragma unroll
        for (int c = 0; c < 4; c++) wmma::fill_fragment(acc[r][c], 0.0f);

    for (int kc = 0; kc < 2; kc++) {              // K chunks of 64
        #pragma unroll
        for (int t = 0; t < 8; t++) {
            int idx = tid + t * 256;
            int r   = idx >> 4;
            int kq  = idx & 15;                   // quad of 4 halves
            int grow = rowBase + r;
            uint2 u = make_uint2(0u, 0u);
            if (grow < NN) {
                if (useX) {
                    float4 v = *(const float4*)&xext[(long long)grow * FF + kc * 64 + kq * 4];
                    u.x = h2u(__floats2half2_rn(v.x, v.y));
                    u.y = h2u(__floats2half2_rn(v.z, v.w));
                } else {
                    u = g_act[grow * MQ + kc * 16 + kq];
                }
            }
            *(uint2*)&As[r * ASTR + kq * 4] = u;
        }
        #pragma unroll
        for (int t = 0; t < 4; t++) {
            int idx = tid + t * 256;
            int k   = idx >> 4;
            int co  = idx & 15;                   // oct of 8 halves
            uint4 v = *(const uint4*)&Wh[(kc * 64 + k) * FF + co * 8];
            *(uint4*)&Ws[k * WSTR + co * 8] = v;
        }
        __syncthreads();

        #pragma unroll
        for (int kk = 0; kk < 4; kk++) {          // K steps of 16
            wmma::fragment<wmma::matrix_a, 16, 16, 16, __half, wmma::row_major> a0, a1;
            wmma::load_matrix_sync(a0, &As[(stripe * 32) * ASTR + kk * 16], ASTR);
            wmma::load_matrix_sync(a1, &As[(stripe * 32 + 16) * ASTR + kk * 16], ASTR);
            #pragma unroll
            for (int c = 0; c < 4; c++) {
                wmma::fragment<wmma::matrix_b, 16, 16, 16, __half, wmma::row_major> b;
                wmma::load_matrix_sync(b, &Ws[(kk * 16) * WSTR + half_ * 64 + c * 16], WSTR);
                wmma::mma_sync(acc[0][c], a0, b, acc[0][c]);
                wmma::mma_sync(acc[1][c], a1, b, acc[1][c]);
            }
        }
        __syncthreads();
    }

    // epilogue in two 64-row passes through shared
    #pragma unroll
    for (int pass = 0; pass < 2; pass++) {
        if ((stripe >> 1) == pass) {
            int localStripe = stripe & 1;
            #pragma unroll
            for (int rt = 0; rt < 2; rt++)
                #pragma unroll
                for (int c = 0; c < 4; c++)
                    wmma::store_matrix_sync(&Cs[(localStripe * 32 + rt * 16) * WSTR + half_ * 64 + c * 16],
                                            acc[rt][c], WSTR, wmma::mem_row_major);
        }
        __syncthreads();
        #pragma unroll
        for (int t = 0; t < 8; t++) {
            int idx = tid + t * 256;               // 64 rows x 32 quads
            int r = idx >> 5;
            int q = idx & 31;
            int grow = rowBase + pass * 64 + r;
            if (grow < NN) {
                float dv = g_dinv[grow];
                float4 v = *(float4*)&Cs[r * WSTR + q * 4];
                uint2 u;
                u.x = h2u(__floats2half2_rn(v.x * dv, v.y * dv));
                u.y = h2u(__floats2half2_rn(v.z * dv, v.w * dv));
                g_msg[grow * MQ + q] = u;
            }
        }
        __syncthreads();
    }
}

// ---------------- aggregation: act[v] = fp16( relu?( dinv[v]*sum msg + b ) ) ----
__global__ void __launch_bounds__(256) k_agg(const float* __restrict__ bias,
                                             int do_relu) {
    int v    = (blockIdx.x * blockDim.x + threadIdx.x) >> 5;  // one warp per node
    int lane = threadIdx.x & 31;
    if (v >= NN) return;

    uint2 mself = g_msg[(v << 5) + lane];
    __half2 c0a = u2h(mself.x), c0b = u2h(mself.y);
    __half2 z = __floats2half2_rn(0.f, 0.f);
    __half2 c1a = z, c1b = z, c2a = z, c2b = z, c3a = z, c3b = z;

    int s = g_rowptr[v];
    int deg = g_rowptr[v + 1] - s;

    for (int base = 0; base < deg; base += 32) {
        int rem = deg - base;
        int n = rem < 32 ? rem : 32;
        int myc = 0;
        if (lane < n) myc = g_col[s + base + lane];            // coalesced prefetch

        int jj = 0;
        for (; jj + 8 <= n; jj += 8) {
            int u0 = __shfl_sync(0xffffffffu, myc, jj);
            int u1 = __shfl_sync(0xffffffffu, myc, jj + 1);
            int u2 = __shfl_sync(0xffffffffu, myc, jj + 2);
            int u3 = __shfl_sync(0xffffffffu, myc, jj + 3);
            int u4 = __shfl_sync(0xffffffffu, myc, jj + 4);
            int u5 = __shfl_sync(0xffffffffu, myc, jj + 5);
            int u6 = __shfl_sync(0xffffffffu, myc, jj + 6);
            int u7 = __shfl_sync(0xffffffffu, myc, jj + 7);
            uint2 m0 = g_msg[(u0 << 5) + lane];
            uint2 m1 = g_msg[(u1 << 5) + lane];
            uint2 m2 = g_msg[(u2 << 5) + lane];
            uint2 m3 = g_msg[(u3 << 5) + lane];
            uint2 m4 = g_msg[(u4 << 5) + lane];
            uint2 m5 = g_msg[(u5 << 5) + lane];
            uint2 m6 = g_msg[(u6 << 5) + lane];
            uint2 m7 = g_msg[(u7 << 5) + lane];
            c0a = __hadd2(c0a, u2h(m0.x)); c0b = __hadd2(c0b, u2h(m0.y));
            c1a = __hadd2(c1a, u2h(m1.x)); c1b = __hadd2(c1b, u2h(m1.y));
            c2a = __hadd2(c2a, u2h(m2.x)); c2b = __hadd2(c2b, u2h(m2.y));
            c3a = __hadd2(c3a, u2h(m3.x)); c3b = __hadd2(c3b, u2h(m3.y));
            c0a = __hadd2(c0a, u2h(m4.x)); c0b = __hadd2(c0b, u2h(m4.y));
            c1a = __hadd2(c1a, u2h(m5.x)); c1b = __hadd2(c1b, u2h(m5.y));
            c2a = __hadd2(c2a, u2h(m6.x)); c2b = __hadd2(c2b, u2h(m6.y));
            c3a = __hadd2(c3a, u2h(m7.x)); c3b = __hadd2(c3b, u2h(m7.y));
        }
        for (; jj + 2 <= n; jj += 2) {
            int u0 = __shfl_sync(0xffffffffu, myc, jj);
            int u1 = __shfl_sync(0xffffffffu, myc, jj + 1);
            uint2 m0 = g_msg[(u0 << 5) + lane];
            uint2 m1 = g_msg[(u1 << 5) + lane];
            c0a = __hadd2(c0a, u2h(m0.x)); c0b = __hadd2(c0b, u2h(m0.y));
            c1a = __hadd2(c1a, u2h(m1.x)); c1b = __hadd2(c1b, u2h(m1.y));
        }
        if (jj < n) {
            int u = __shfl_sync(0xffffffffu, myc, jj);
            uint2 m = g_msg[(u << 5) + lane];
            c2a = __hadd2(c2a, u2h(m.x)); c2b = __hadd2(c2b, u2h(m.y));
        }
    }

    float2 f0a = __half22float2(c0a), f1a = __half22float2(c1a);
    float2 f2a = __half22float2(c2a), f3a = __half22float2(c3a);
    float2 f0b = __half22float2(c0b), f1b = __half22float2(c1b);
    float2 f2b = __half22float2(c2b), f3b = __half22float2(c3b);

    float  dv = g_dinv[v];
    float4 b  = *(const float4*)&bias[lane * 4];
    float4 acc;
    acc.x = (f0a.x + f1a.x + f2a.x + f3a.x) * dv + b.x;
    acc.y = (f0a.y + f1a.y + f2a.y + f3a.y) * dv + b.y;
    acc.z = (f0b.x + f1b.x + f2b.x + f3b.x) * dv + b.z;
    acc.w = (f0b.y + f1b.y + f2b.y + f3b.y) * dv + b.w;
    if (do_relu) {
        acc.x = fmaxf(acc.x, 0.f); acc.y = fmaxf(acc.y, 0.f);
        acc.z = fmaxf(acc.z, 0.f); acc.w = fmaxf(acc.w, 0.f);
    }
    uint2 u;
    u.x = h2u(__floats2half2_rn(acc.x, acc.y));
    u.y = h2u(__floats2half2_rn(acc.z, acc.w));
    g_act[(v << 5) + lane] = u;
}

// ---------------- mean pooling + classifier (fused); reads fp16 g_act ----------------
__device__ __forceinline__ int lower_bound_idx(const void* a, int val, int is64) {
    int lo = 0, hi = NN;
    while (lo < hi) {
        int mid = (lo + hi) >> 1;
        if (load_idx(a, mid, is64) < val) lo = mid + 1; else hi = mid;
    }
    return lo;
}

__global__ void __launch_bounds__(1024) k_pool(const void* __restrict__ batch,
                                               const float* __restrict__ Wc,
                                               const float* __restrict__ bc,
                                               float* __restrict__ out) {
    __shared__ int se[2];
    __shared__ float red[8][FF];
    __shared__ float pooled[FF];
    int g = blockIdx.x;
    if (threadIdx.x == 0) {
        int is64 = g_is64;
        se[0] = lower_bound_idx(batch, g, is64);
        se[1] = lower_bound_idx(batch, g + 1, is64);
    }
    __syncthreads();
    int s = se[0], e = se[1];
    int col = threadIdx.x & 127;
    int rc  = threadIdx.x >> 7;
    const __half* h = (const __half*)g_act;
    float sum = 0.f;
    for (int i = s + rc; i < e; i += 8) sum += __half2float(h[i * FF + col]);
    red[rc][col] = sum;
    __syncthreads();
    if (rc == 0) {
        float t = 0.f;
        #pragma unroll
        for (int k = 0; k < 8; k++) t += red[k][col];
        float cnt = (float)(e - s);
        pooled[col] = t / fmaxf(cnt, 1.0f);
    }
    __syncthreads();
    if (threadIdx.x < NC) {
        int c = threadIdx.x;
        float sumc = bc[c];
        #pragma unroll 8
        for (int k = 0; k < FF; k++)
            sumc += pooled[k] * Wc[k * NC + c];
        out[g * NC + c] = sumc;
    }
}

// ---------------- launch ----------------
extern "C" void kernel_launch(void* const* d_in, const int* in_sizes, int n_in,
                              void* d_out, int out_size) {
    const float* x  = (const float*)d_in[0];
    const void*  ei = d_in[1];
    const void*  batch = d_in[2];
    const float* W0 = (const float*)d_in[3];
    const float* b0 = (const float*)d_in[4];
    const float* W1 = (const float*)d_in[5];
    const float* b1 = (const float*)d_in[6];
    const float* W2 = (const float*)d_in[7];
    const float* b2 = (const float*)d_in[8];
    const float* Wc = (const float*)d_in[9];
    const float* bc = (const float*)d_in[10];
    float* out = (float*)d_out;

    const int gemm_grid = (NN + BM - 1) / BM;
    const int agg_grid  = (NN + 7) / 8;

    k_init <<<(NN + 255) / 256, 256>>>((const int*)ei, W0, W1, W2);   // 1
    k_count<<<(NE + 255) / 256, 256>>>(ei);                           // 2
    k_scan <<<NBLK, SCAN_B>>>();                                      // 3
    k_gemm <<<gemm_grid, 256>>>(x, 0, 0);                             // 4 (profiled)
    k_fill <<<(NE + 255) / 256, 256>>>(ei);                           // 5
    k_agg  <<<agg_grid,  256>>>(b0, 1);                               // 6
    k_gemm <<<gemm_grid, 256>>>(x, 1, 1);
    k_agg  <<<agg_grid,  256>>>(b1, 1);
    k_gemm <<<gemm_grid, 256>>>(x, 1, 2);
    k_agg  <<<agg_grid,  256>>>(b2, 0);

    k_pool<<<NG, 1024>>>(batch, Wc, bc, out);
}

// round 15
// speedup vs baseline: 2.0744x; 1.0515x over previous
#include <cuda_runtime.h>
#include <cuda_fp16.h>
#include <mma.h>

using namespace nvcuda;

#define NN 50000
#define NE 800000
#define FF 128
#define MQ 32                      // uint2 (4 halves) per fp16 row
#define NG 64
#define NC 16
#define SCAN_B 512
#define NBLK ((NN + SCAN_B - 1) / SCAN_B)   // 98

// GEMM tiling (fp16 HMMA): BM=64 rows, full K=128 in one chunk, 8 warps.
#define BM 64
#define TSTR 136                   // smem row stride in halves (128 + 8 skew)
#define GEMM_SMEM 52224            // A 64*136*2 + W 128*136*2; Cs (64*136*4=34816) reuses

// ---------------- scratch (static device globals; no allocation) ----------------
__device__ int      g_is64;
__device__ int      g_counts[NN];
__device__ int      g_fill[NN];      // absolute write cursor
__device__ int      g_rowptr[NN + 1];
__device__ int      g_col[NE];
__device__ float    g_dinv[NN];
__device__ __half   g_Wh[3][FF * FF];  // fp16 weights (converted in k_init)
__device__ uint2    g_msg[NN * MQ];    // fp16 messages (dinv-scaled GEMM output)
__device__ uint2    g_act[NN * MQ];    // fp16 activations (agg output, layer input)
__device__ volatile int g_sflag[NBLK]; // scan publish flags
__device__ volatile int g_sval[NBLK];  // scan block sums

// bit reinterpretation helpers
__device__ __forceinline__ unsigned h2u(__half2 h) { return *reinterpret_cast<unsigned*>(&h); }
__device__ __forceinline__ __half2 u2h(unsigned u) { return *reinterpret_cast<__half2*>(&u); }

// dtype-agnostic index load (edge_index / batch may be int32 or int64)
__device__ __forceinline__ int load_idx(const void* p, long long i, int is64) {
    if (is64) return (int)((const long long*)p)[i];
    return ((const int*)p)[i];
}

// ---------------- init: zero counts/flags + dtype detect + W fp16 conversion ----------------
__global__ void k_init(const int* __restrict__ w32,
                       const float* __restrict__ W0,
                       const float* __restrict__ W1,
                       const float* __restrict__ W2) {
    int i = blockIdx.x * blockDim.x + threadIdx.x;
    if (i < NN) g_counts[i] = 0;
    if (i < NBLK) g_sflag[i] = 0;
    if (i < FF * FF) {
        g_Wh[0][i] = __float2half_rn(W0[i]);
        g_Wh[1][i] = __float2half_rn(W1[i]);
        g_Wh[2][i] = __float2half_rn(W2[i]);
    }
    if (i == 0) {
        int nz = 0;
        #pragma unroll
        for (int k = 0; k < 16; k++) nz |= w32[2 * k + 1];
        g_is64 = (nz == 0) ? 1 : 0;
    }
}

__global__ void k_count(const void* __restrict__ ei) {
    int i = blockIdx.x * blockDim.x + threadIdx.x;
    if (i >= NE) return;
    int d = load_idx(ei, (long long)NE + i, g_is64);
    atomicAdd(&g_counts[d], 1);
}

// single-pass scan with decoupled lookback: rowptr, cursor, dinv in one kernel.
__global__ void __launch_bounds__(SCAN_B) k_scan() {
    __shared__ int warp_sums[SCAN_B / 32];
    __shared__ int s_off;
    int b = blockIdx.x;
    int i = b * SCAN_B + threadIdx.x;
    int v = (i < NN) ? g_counts[i] : 0;
    int lane = threadIdx.x & 31;
    int wid  = threadIdx.x >> 5;

    int x = v;
    #pragma unroll
    for (int off = 1; off < 32; off <<= 1) {
        int t = __shfl_up_sync(0xffffffffu, x, off);
        if (lane >= off) x += t;
    }
    if (lane == 31) warp_sums[wid] = x;
    __syncthreads();
    if (wid == 0) {
        int w = (lane < SCAN_B / 32) ? warp_sums[lane] : 0;
        #pragma unroll
        for (int off = 1; off < SCAN_B / 32; off <<= 1) {
            int t = __shfl_up_sync(0xffffffffu, w, off);
            if (lane >= off) w += t;
        }
        if (lane < SCAN_B / 32) warp_sums[lane] = w;
    }
    __syncthreads();
    int base = (wid > 0) ? warp_sums[wid - 1] : 0;
    int incl = base + x;

    if (threadIdx.x == SCAN_B - 1) {
        g_sval[b] = incl;
        __threadfence();
        g_sflag[b] = 1;
    }
    if (wid == 0) {
        int acc = 0;
        for (int k = lane; k < b; k += 32) {
            while (g_sflag[k] == 0) { }
            acc += g_sval[k];
        }
        #pragma unroll
        for (int off = 16; off; off >>= 1) acc += __shfl_down_sync(0xffffffffu, acc, off);
        if (lane == 0) s_off = acc;
    }
    __syncthreads();

    if (i < NN) {
        int rp = s_off + incl - v;
        g_rowptr[i] = rp;
        g_fill[i]   = rp;
        g_dinv[i]   = rsqrtf((float)(v + 1));
    }
    if (i == 0) g_rowptr[NN] = NE;
}

__global__ void k_fill(const void* __restrict__ ei) {
    int i = blockIdx.x * blockDim.x + threadIdx.x;
    if (i >= NE) return;
    int is64 = g_is64;
    int s = load_idx(ei, (long long)i, is64);
    int d = load_idx(ei, (long long)NE + i, is64);
    int pos = atomicAdd(&g_fill[d], 1);
    g_col[pos] = s;
}

// ---------------- GEMM (fp16 HMMA): g_msg[r] = fp16( (src[r] @ W) * dinv[r] ) ----------------
// BM=64 rows, full K=128 single chunk, 8 warps. Dynamic smem (52224 B).
__global__ void __launch_bounds__(256) k_gemm(const float* __restrict__ xext,
                                              int srcSel,
                                              int wSel) {
    extern __shared__ __align__(16) char smraw[];
    __half* As = (__half*)smraw;                  // 64 x TSTR
    __half* Ws = (__half*)smraw + BM * TSTR;      // 128 x TSTR
    float*  Cs = (float*)smraw;                   // 64 x TSTR floats (epilogue reuse)

    const bool useX = (srcSel == 0);
    const __half* Wh = g_Wh[wSel];
    int tid = threadIdx.x;
    int wid = tid >> 5;
    int stripe = wid >> 1;        // 0..3 -> rows [stripe*16, +16)
    int half_  = wid & 1;         // 0..1 -> cols [half_*64, +64)
    int rowBase = blockIdx.x * BM;

    // Load A: 64 rows x 128 halves = 64x32 quads, 8 per thread.
    #pragma unroll
    for (int t = 0; t < 8; t++) {
        int idx = tid + t * 256;
        int r   = idx >> 5;
        int q   = idx & 31;                       // quad of 4 halves
        int grow = rowBase + r;
        uint2 u = make_uint2(0u, 0u);
        if (grow < NN) {
            if (useX) {
                float4 v = *(const float4*)&xext[(long long)grow * FF + q * 4];
                u.x = h2u(__floats2half2_rn(v.x, v.y));
                u.y = h2u(__floats2half2_rn(v.z, v.w));
            } else {
                u = g_act[(grow << 5) + q];
            }
        }
        *(uint2*)&As[r * TSTR + q * 4] = u;
    }
    // Load W: 128 rows x 128 halves = 128x16 octs, 8 per thread.
    #pragma unroll
    for (int t = 0; t < 8; t++) {
        int idx = tid + t * 256;
        int k   = idx >> 4;
        int co  = idx & 15;                       // oct of 8 halves
        uint4 v = *(const uint4*)&Wh[k * FF + co * 8];
        *(uint4*)&Ws[k * TSTR + co * 8] = v;
    }
    __syncthreads();

    wmma::fragment<wmma::accumulator, 16, 16, 16, float> acc[4];
    #pragma unroll
    for (int c = 0; c < 4; c++) wmma::fill_fragment(acc[c], 0.0f);

    #pragma unroll
    for (int kk = 0; kk < 8; kk++) {              // K steps of 16
        wmma::fragment<wmma::matrix_a, 16, 16, 16, __half, wmma::row_major> a;
        wmma::load_matrix_sync(a, &As[(stripe * 16) * TSTR + kk * 16], TSTR);
        #pragma unroll
        for (int c = 0; c < 4; c++) {
            wmma::fragment<wmma::matrix_b, 16, 16, 16, __half, wmma::row_major> b;
            wmma::load_matrix_sync(b, &Ws[(kk * 16) * TSTR + half_ * 64 + c * 16], TSTR);
            wmma::mma_sync(acc[c], a, b, acc[c]);
        }
    }
    __syncthreads();

    // epilogue: frags -> Cs -> dinv scale -> fp16 -> global
    #pragma unroll
    for (int c = 0; c < 4; c++)
        wmma::store_matrix_sync(&Cs[(stripe * 16) * TSTR + half_ * 64 + c * 16],
                                acc[c], TSTR, wmma::mem_row_major);
    __syncthreads();

    #pragma unroll
    for (int t = 0; t < 8; t++) {
        int idx = tid + t * 256;                  // 64 rows x 32 quads
        int r = idx >> 5;
        int q = idx & 31;
        int grow = rowBase + r;
        if (grow < NN) {
            float dv = g_dinv[grow];
            float4 v = *(float4*)&Cs[r * TSTR + q * 4];
            uint2 u;
            u.x = h2u(__floats2half2_rn(v.x * dv, v.y * dv));
            u.y = h2u(__floats2half2_rn(v.z * dv, v.w * dv));
            g_msg[(grow << 5) + q] = u;
        }
    }
}

// ---------------- aggregation: act[v] = fp16( relu?( dinv[v]*sum msg + b ) ) ----
__global__ void __launch_bounds__(256) k_agg(const float* __restrict__ bias,
                                             int do_relu) {
    int v    = (blockIdx.x * blockDim.x + threadIdx.x) >> 5;  // one warp per node
    int lane = threadIdx.x & 31;
    if (v >= NN) return;

    uint2 mself = g_msg[(v << 5) + lane];
    __half2 c0a = u2h(mself.x), c0b = u2h(mself.y);
    __half2 z = __floats2half2_rn(0.f, 0.f);
    __half2 c1a = z, c1b = z, c2a = z, c2b = z, c3a = z, c3b = z;

    int s = g_rowptr[v];
    int deg = g_rowptr[v + 1] - s;

    for (int base = 0; base < deg; base += 32) {
        int rem = deg - base;
        int n = rem < 32 ? rem : 32;
        int myc = 0;
        if (lane < n) myc = g_col[s + base + lane];            // coalesced prefetch

        int jj = 0;
        for (; jj + 8 <= n; jj += 8) {
            int u0 = __shfl_sync(0xffffffffu, myc, jj);
            int u1 = __shfl_sync(0xffffffffu, myc, jj + 1);
            int u2 = __shfl_sync(0xffffffffu, myc, jj + 2);
            int u3 = __shfl_sync(0xffffffffu, myc, jj + 3);
            int u4 = __shfl_sync(0xffffffffu, myc, jj + 4);
            int u5 = __shfl_sync(0xffffffffu, myc, jj + 5);
            int u6 = __shfl_sync(0xffffffffu, myc, jj + 6);
            int u7 = __shfl_sync(0xffffffffu, myc, jj + 7);
            uint2 m0 = g_msg[(u0 << 5) + lane];
            uint2 m1 = g_msg[(u1 << 5) + lane];
            uint2 m2 = g_msg[(u2 << 5) + lane];
            uint2 m3 = g_msg[(u3 << 5) + lane];
            uint2 m4 = g_msg[(u4 << 5) + lane];
            uint2 m5 = g_msg[(u5 << 5) + lane];
            uint2 m6 = g_msg[(u6 << 5) + lane];
            uint2 m7 = g_msg[(u7 << 5) + lane];
            c0a = __hadd2(c0a, u2h(m0.x)); c0b = __hadd2(c0b, u2h(m0.y));
            c1a = __hadd2(c1a, u2h(m1.x)); c1b = __hadd2(c1b, u2h(m1.y));
            c2a = __hadd2(c2a, u2h(m2.x)); c2b = __hadd2(c2b, u2h(m2.y));
            c3a = __hadd2(c3a, u2h(m3.x)); c3b = __hadd2(c3b, u2h(m3.y));
            c0a = __hadd2(c0a, u2h(m4.x)); c0b = __hadd2(c0b, u2h(m4.y));
            c1a = __hadd2(c1a, u2h(m5.x)); c1b = __hadd2(c1b, u2h(m5.y));
            c2a = __hadd2(c2a, u2h(m6.x)); c2b = __hadd2(c2b, u2h(m6.y));
            c3a = __hadd2(c3a, u2h(m7.x)); c3b = __hadd2(c3b, u2h(m7.y));
        }
        for (; jj + 2 <= n; jj += 2) {
            int u0 = __shfl_sync(0xffffffffu, myc, jj);
            int u1 = __shfl_sync(0xffffffffu, myc, jj + 1);
            uint2 m0 = g_msg[(u0 << 5) + lane];
            uint2 m1 = g_msg[(u1 << 5) + lane];
            c0a = __hadd2(c0a, u2h(m0.x)); c0b = __hadd2(c0b, u2h(m0.y));
            c1a = __hadd2(c1a, u2h(m1.x)); c1b = __hadd2(c1b, u2h(m1.y));
        }
        if (jj < n) {
            int u = __shfl_sync(0xffffffffu, myc, jj);
            uint2 m = g_msg[(u << 5) + lane];
            c2a = __hadd2(c2a, u2h(m.x)); c2b = __hadd2(c2b, u2h(m.y));
        }
    }

    float2 f0a = __half22float2(c0a), f1a = __half22float2(c1a);
    float2 f2a = __half22float2(c2a), f3a = __half22float2(c3a);
    float2 f0b = __half22float2(c0b), f1b = __half22float2(c1b);
    float2 f2b = __half22float2(c2b), f3b = __half22float2(c3b);

    float  dv = g_dinv[v];
    float4 b  = *(const float4*)&bias[lane * 4];
    float4 acc;
    acc.x = (f0a.x + f1a.x + f2a.x + f3a.x) * dv + b.x;
    acc.y = (f0a.y + f1a.y + f2a.y + f3a.y) * dv + b.y;
    acc.z = (f0b.x + f1b.x + f2b.x + f3b.x) * dv + b.z;
    acc.w = (f0b.y + f1b.y + f2b.y + f3b.y) * dv + b.w;
    if (do_relu) {
        acc.x = fmaxf(acc.x, 0.f); acc.y = fmaxf(acc.y, 0.f);
        acc.z = fmaxf(acc.z, 0.f); acc.w = fmaxf(acc.w, 0.f);
    }
    uint2 u;
    u.x = h2u(__floats2half2_rn(acc.x, acc.y));
    u.y = h2u(__floats2half2_rn(acc.z, acc.w));
    g_act[(v << 5) + lane] = u;
}

// ---------------- mean pooling + classifier (fused); reads fp16 g_act ----------------
__device__ __forceinline__ int lower_bound_idx(const void* a, int val, int is64) {
    int lo = 0, hi = NN;
    while (lo < hi) {
        int mid = (lo + hi) >> 1;
        if (load_idx(a, mid, is64) < val) lo = mid + 1; else hi = mid;
    }
    return lo;
}

__global__ void __launch_bounds__(1024) k_pool(const void* __restrict__ batch,
                                               const float* __restrict__ Wc,
                                               const float* __restrict__ bc,
                                               float* __restrict__ out) {
    __shared__ int se[2];
    __shared__ float red[8][FF];
    __shared__ float pooled[FF];
    int g = blockIdx.x;
    if (threadIdx.x == 0) {
        int is64 = g_is64;
        se[0] = lower_bound_idx(batch, g, is64);
        se[1] = lower_bound_idx(batch, g + 1, is64);
    }
    __syncthreads();
    int s = se[0], e = se[1];
    int col = threadIdx.x & 127;
    int rc  = threadIdx.x >> 7;
    const __half* h = (const __half*)g_act;
    float sum = 0.f;
    for (int i = s + rc; i < e; i += 8) sum += __half2float(h[i * FF + col]);
    red[rc][col] = sum;
    __syncthreads();
    if (rc == 0) {
        float t = 0.f;
        #pragma unroll
        for (int k = 0; k < 8; k++) t += red[k][col];
        float cnt = (float)(e - s);
        pooled[col] = t / fmaxf(cnt, 1.0f);
    }
    __syncthreads();
    if (threadIdx.x < NC) {
        int c = threadIdx.x;
        float sumc = bc[c];
        #pragma unroll 8
        for (int k = 0; k < FF; k++)
            sumc += pooled[k] * Wc[k * NC + c];
        out[g * NC + c] = sumc;
    }
}

// ---------------- launch ----------------
extern "C" void kernel_launch(void* const* d_in, const int* in_sizes, int n_in,
                              void* d_out, int out_size) {
    const float* x  = (const float*)d_in[0];
    const void*  ei = d_in[1];
    const void*  batch = d_in[2];
    const float* W0 = (const float*)d_in[3];
    const float* b0 = (const float*)d_in[4];
    const float* W1 = (const float*)d_in[5];
    const float* b1 = (const float*)d_in[6];
    const float* W2 = (const float*)d_in[7];
    const float* b2 = (const float*)d_in[8];
    const float* Wc = (const float*)d_in[9];
    const float* bc = (const float*)d_in[10];
    float* out = (float*)d_out;

    static int attr_done = 0;
    if (!attr_done) {
        cudaFuncSetAttribute(k_gemm, cudaFuncAttributeMaxDynamicSharedMemorySize, GEMM_SMEM);
        attr_done = 1;
    }

    const int gemm_grid = (NN + BM - 1) / BM;
    const int agg_grid  = (NN + 7) / 8;

    k_init <<<(NN + 255) / 256, 256>>>((const int*)ei, W0, W1, W2);   // 1
    k_count<<<(NE + 255) / 256, 256>>>(ei);                           // 2
    k_scan <<<NBLK, SCAN_B>>>();                                      // 3
    k_gemm <<<gemm_grid, 256, GEMM_SMEM>>>(x, 0, 0);                  // 4 (profiled)
    k_fill <<<(NE + 255) / 256, 256>>>(ei);                           // 5
    k_agg  <<<agg_grid,  256>>>(b0, 1);                               // 6
    k_gemm <<<gemm_grid, 256, GEMM_SMEM>>>(x, 1, 1);
    k_agg  <<<agg_grid,  256>>>(b1, 1);
    k_gemm <<<gemm_grid, 256, GEMM_SMEM>>>(x, 1, 2);
    k_agg  <<<agg_grid,  256>>>(b2, 0);

    k_pool<<<NG, 1024>>>(batch, Wc, bc, out);
}

// round 16
// speedup vs baseline: 2.0948x; 1.0099x over previous
#include <cuda_runtime.h>
#include <cuda_fp16.h>
#include <mma.h>

using namespace nvcuda;

#define NN 50000
#define NE 800000
#define FF 128
#define MQ 32                      // uint2 (4 halves) per fp16 row
#define NG 64
#define NC 16
#define SCAN_B 512
#define NBLK ((NN + SCAN_B - 1) / SCAN_B)   // 98
#define FILLB 200                  // fill-role blocks appended to gemm0 grid

// GEMM tiling (fp16 HMMA): BM=64 rows, full K=128 in one chunk, 8 warps.
#define BM 64
#define TSTR 136                   // smem row stride in halves (128 + 8 skew)
#define GEMM_SMEM 52224            // A 64*136*2 + W 128*136*2; Cs (64*136*4) reuses

// ---------------- scratch (static device globals; no allocation) ----------------
__device__ int      g_is64;
__device__ int      g_counts[NN];
__device__ int      g_fill[NN];      // absolute write cursor
__device__ int      g_rowptr[NN + 1];
__device__ int      g_col[NE];
__device__ float    g_dinv[NN];
__device__ __half   g_Wh[3][FF * FF];  // fp16 weights (converted in k_init)
__device__ uint2    g_msg[NN * MQ];    // fp16 messages (dinv-scaled GEMM output)
__device__ uint2    g_act[NN * MQ];    // fp16 activations (agg output, layer input)
__device__ volatile int g_sflag[NBLK]; // scan publish flags
__device__ volatile int g_sval[NBLK];  // scan block sums

// bit reinterpretation helpers
__device__ __forceinline__ unsigned h2u(__half2 h) { return *reinterpret_cast<unsigned*>(&h); }
__device__ __forceinline__ __half2 u2h(unsigned u) { return *reinterpret_cast<__half2*>(&u); }

// dtype-agnostic index load (edge_index / batch may be int32 or int64)
__device__ __forceinline__ int load_idx(const void* p, long long i, int is64) {
    if (is64) return (int)((const long long*)p)[i];
    return ((const int*)p)[i];
}

// ---------------- init: zero counts/flags + dtype detect + W fp16 conversion ----------------
__global__ void k_init(const int* __restrict__ w32,
                       const float* __restrict__ W0,
                       const float* __restrict__ W1,
                       const float* __restrict__ W2) {
    int i = blockIdx.x * blockDim.x + threadIdx.x;
    if (i < NN) g_counts[i] = 0;
    if (i < NBLK) g_sflag[i] = 0;
    if (i < FF * FF) {
        g_Wh[0][i] = __float2half_rn(W0[i]);
        g_Wh[1][i] = __float2half_rn(W1[i]);
        g_Wh[2][i] = __float2half_rn(W2[i]);
    }
    if (i == 0) {
        int nz = 0;
        #pragma unroll
        for (int k = 0; k < 16; k++) nz |= w32[2 * k + 1];
        g_is64 = (nz == 0) ? 1 : 0;
    }
}

__global__ void k_count(const void* __restrict__ ei) {
    int i = blockIdx.x * blockDim.x + threadIdx.x;
    if (i >= NE) return;
    int d = load_idx(ei, (long long)NE + i, g_is64);
    atomicAdd(&g_counts[d], 1);
}

// single-pass scan with decoupled lookback: rowptr, cursor, dinv in one kernel.
__global__ void __launch_bounds__(SCAN_B) k_scan() {
    __shared__ int warp_sums[SCAN_B / 32];
    __shared__ int s_off;
    int b = blockIdx.x;
    int i = b * SCAN_B + threadIdx.x;
    int v = (i < NN) ? g_counts[i] : 0;
    int lane = threadIdx.x & 31;
    int wid  = threadIdx.x >> 5;

    int x = v;
    #pragma unroll
    for (int off = 1; off < 32; off <<= 1) {
        int t = __shfl_up_sync(0xffffffffu, x, off);
        if (lane >= off) x += t;
    }
    if (lane == 31) warp_sums[wid] = x;
    __syncthreads();
    if (wid == 0) {
        int w = (lane < SCAN_B / 32) ? warp_sums[lane] : 0;
        #pragma unroll
        for (int off = 1; off < SCAN_B / 32; off <<= 1) {
            int t = __shfl_up_sync(0xffffffffu, w, off);
            if (lane >= off) w += t;
        }
        if (lane < SCAN_B / 32) warp_sums[lane] = w;
    }
    __syncthreads();
    int base = (wid > 0) ? warp_sums[wid - 1] : 0;
    int incl = base + x;

    if (threadIdx.x == SCAN_B - 1) {
        g_sval[b] = incl;
        __threadfence();
        g_sflag[b] = 1;
    }
    if (wid == 0) {
        int acc = 0;
        for (int k = lane; k < b; k += 32) {
            while (g_sflag[k] == 0) { }
            acc += g_sval[k];
        }
        #pragma unroll
        for (int off = 16; off; off >>= 1) acc += __shfl_down_sync(0xffffffffu, acc, off);
        if (lane == 0) s_off = acc;
    }
    __syncthreads();

    if (i < NN) {
        int rp = s_off + incl - v;
        g_rowptr[i] = rp;
        g_fill[i]   = rp;
        g_dinv[i]   = rsqrtf((float)(v + 1));
    }
    if (i == 0) g_rowptr[NN] = NE;
}

// ---------------- GEMM (fp16 HMMA) + optional fill role ----------------
// Blocks [0, gridDim.x - nFill): msg[r] = fp16( (src[r] @ W) * dinv[r] ).
// Blocks [gridDim.x - nFill, gridDim.x): CSR fill (grid-stride over edges).
__global__ void __launch_bounds__(256) k_gemm(const float* __restrict__ xext,
                                              int srcSel,
                                              int wSel,
                                              const void* __restrict__ ei,
                                              int nFill) {
    extern __shared__ __align__(16) char smraw[];

    int gemmBlocks = gridDim.x - nFill;
    if (blockIdx.x >= gemmBlocks) {
        // ---- fill role: scatter edges into CSR via absolute cursor ----
        int is64 = g_is64;
        int fb = blockIdx.x - gemmBlocks;
        for (long long i = (long long)fb * blockDim.x + threadIdx.x; i < NE;
             i += (long long)nFill * blockDim.x) {
            int s = load_idx(ei, i, is64);
            int d = load_idx(ei, (long long)NE + i, is64);
            int pos = atomicAdd(&g_fill[d], 1);
            g_col[pos] = s;
        }
        return;
    }

    __half* As = (__half*)smraw;                  // 64 x TSTR
    __half* Ws = (__half*)smraw + BM * TSTR;      // 128 x TSTR
    float*  Cs = (float*)smraw;                   // 64 x TSTR floats (epilogue reuse)

    const bool useX = (srcSel == 0);
    const __half* Wh = g_Wh[wSel];
    int tid = threadIdx.x;
    int wid = tid >> 5;
    int stripe = wid >> 1;        // 0..3 -> rows [stripe*16, +16)
    int half_  = wid & 1;         // 0..1 -> cols [half_*64, +64)
    int rowBase = blockIdx.x * BM;

    // Load A: 64 rows x 128 halves = 64x32 quads, 8 per thread.
    #pragma unroll
    for (int t = 0; t < 8; t++) {
        int idx = tid + t * 256;
        int r   = idx >> 5;
        int q   = idx & 31;                       // quad of 4 halves
        int grow = rowBase + r;
        uint2 u = make_uint2(0u, 0u);
        if (grow < NN) {
            if (useX) {
                float4 v = *(const float4*)&xext[(long long)grow * FF + q * 4];
                u.x = h2u(__floats2half2_rn(v.x, v.y));
                u.y = h2u(__floats2half2_rn(v.z, v.w));
            } else {
                u = g_act[(grow << 5) + q];
            }
        }
        *(uint2*)&As[r * TSTR + q * 4] = u;
    }
    // Load W: 128 rows x 128 halves = 128x16 octs, 8 per thread.
    #pragma unroll
    for (int t = 0; t < 8; t++) {
        int idx = tid + t * 256;
        int k   = idx >> 4;
        int co  = idx & 15;                       // oct of 8 halves
        uint4 v = *(const uint4*)&Wh[k * FF + co * 8];
        *(uint4*)&Ws[k * TSTR + co * 8] = v;
    }
    __syncthreads();

    wmma::fragment<wmma::accumulator, 16, 16, 16, float> acc[4];
    #pragma unroll
    for (int c = 0; c < 4; c++) wmma::fill_fragment(acc[c], 0.0f);

    #pragma unroll
    for (int kk = 0; kk < 8; kk++) {              // K steps of 16
        wmma::fragment<wmma::matrix_a, 16, 16, 16, __half, wmma::row_major> a;
        wmma::load_matrix_sync(a, &As[(stripe * 16) * TSTR + kk * 16], TSTR);
        #pragma unroll
        for (int c = 0; c < 4; c++) {
            wmma::fragment<wmma::matrix_b, 16, 16, 16, __half, wmma::row_major> b;
            wmma::load_matrix_sync(b, &Ws[(kk * 16) * TSTR + half_ * 64 + c * 16], TSTR);
            wmma::mma_sync(acc[c], a, b, acc[c]);
        }
    }
    __syncthreads();

    // epilogue: frags -> Cs -> dinv scale -> fp16 -> global
    #pragma unroll
    for (int c = 0; c < 4; c++)
        wmma::store_matrix_sync(&Cs[(stripe * 16) * TSTR + half_ * 64 + c * 16],
                                acc[c], TSTR, wmma::mem_row_major);
    __syncthreads();

    #pragma unroll
    for (int t = 0; t < 8; t++) {
        int idx = tid + t * 256;                  // 64 rows x 32 quads
        int r = idx >> 5;
        int q = idx & 31;
        int grow = rowBase + r;
        if (grow < NN) {
            float dv = g_dinv[grow];
            float4 v = *(float4*)&Cs[r * TSTR + q * 4];
            uint2 u;
            u.x = h2u(__floats2half2_rn(v.x * dv, v.y * dv));
            u.y = h2u(__floats2half2_rn(v.z * dv, v.w * dv));
            g_msg[(grow << 5) + q] = u;
        }
    }
}

// ---------------- aggregation: act[v] = fp16( relu?( dinv[v]*sum msg + b ) ) ----
__global__ void __launch_bounds__(256) k_agg(const float* __restrict__ bias,
                                             int do_relu) {
    int v    = (blockIdx.x * blockDim.x + threadIdx.x) >> 5;  // one warp per node
    int lane = threadIdx.x & 31;
    if (v >= NN) return;

    uint2 mself = g_msg[(v << 5) + lane];
    __half2 c0a = u2h(mself.x), c0b = u2h(mself.y);
    __half2 z = __floats2half2_rn(0.f, 0.f);
    __half2 c1a = z, c1b = z, c2a = z, c2b = z, c3a = z, c3b = z;

    int s = g_rowptr[v];
    int deg = g_rowptr[v + 1] - s;

    for (int base = 0; base < deg; base += 32) {
        int rem = deg - base;
        int n = rem < 32 ? rem : 32;
        int myc = 0;
        if (lane < n) myc = g_col[s + base + lane];            // coalesced prefetch

        int jj = 0;
        for (; jj + 8 <= n; jj += 8) {
            int u0 = __shfl_sync(0xffffffffu, myc, jj);
            int u1 = __shfl_sync(0xffffffffu, myc, jj + 1);
            int u2 = __shfl_sync(0xffffffffu, myc, jj + 2);
            int u3 = __shfl_sync(0xffffffffu, myc, jj + 3);
            int u4 = __shfl_sync(0xffffffffu, myc, jj + 4);
            int u5 = __shfl_sync(0xffffffffu, myc, jj + 5);
            int u6 = __shfl_sync(0xffffffffu, myc, jj + 6);
            int u7 = __shfl_sync(0xffffffffu, myc, jj + 7);
            uint2 m0 = g_msg[(u0 << 5) + lane];
            uint2 m1 = g_msg[(u1 << 5) + lane];
            uint2 m2 = g_msg[(u2 << 5) + lane];
            uint2 m3 = g_msg[(u3 << 5) + lane];
            uint2 m4 = g_msg[(u4 << 5) + lane];
            uint2 m5 = g_msg[(u5 << 5) + lane];
            uint2 m6 = g_msg[(u6 << 5) + lane];
            uint2 m7 = g_msg[(u7 << 5) + lane];
            c0a = __hadd2(c0a, u2h(m0.x)); c0b = __hadd2(c0b, u2h(m0.y));
            c1a = __hadd2(c1a, u2h(m1.x)); c1b = __hadd2(c1b, u2h(m1.y));
            c2a = __hadd2(c2a, u2h(m2.x)); c2b = __hadd2(c2b, u2h(m2.y));
            c3a = __hadd2(c3a, u2h(m3.x)); c3b = __hadd2(c3b, u2h(m3.y));
            c0a = __hadd2(c0a, u2h(m4.x)); c0b = __hadd2(c0b, u2h(m4.y));
            c1a = __hadd2(c1a, u2h(m5.x)); c1b = __hadd2(c1b, u2h(m5.y));
            c2a = __hadd2(c2a, u2h(m6.x)); c2b = __hadd2(c2b, u2h(m6.y));
            c3a = __hadd2(c3a, u2h(m7.x)); c3b = __hadd2(c3b, u2h(m7.y));
        }
        for (; jj + 2 <= n; jj += 2) {
            int u0 = __shfl_sync(0xffffffffu, myc, jj);
            int u1 = __shfl_sync(0xffffffffu, myc, jj + 1);
            uint2 m0 = g_msg[(u0 << 5) + lane];
            uint2 m1 = g_msg[(u1 << 5) + lane];
            c0a = __hadd2(c0a, u2h(m0.x)); c0b = __hadd2(c0b, u2h(m0.y));
            c1a = __hadd2(c1a, u2h(m1.x)); c1b = __hadd2(c1b, u2h(m1.y));
        }
        if (jj < n) {
            int u = __shfl_sync(0xffffffffu, myc, jj);
            uint2 m = g_msg[(u << 5) + lane];
            c2a = __hadd2(c2a, u2h(m.x)); c2b = __hadd2(c2b, u2h(m.y));
        }
    }

    float2 f0a = __half22float2(c0a), f1a = __half22float2(c1a);
    float2 f2a = __half22float2(c2a), f3a = __half22float2(c3a);
    float2 f0b = __half22float2(c0b), f1b = __half22float2(c1b);
    float2 f2b = __half22float2(c2b), f3b = __half22float2(c3b);

    float  dv = g_dinv[v];
    float4 b  = *(const float4*)&bias[lane * 4];
    float4 acc;
    acc.x = (f0a.x + f1a.x + f2a.x + f3a.x) * dv + b.x;
    acc.y = (f0a.y + f1a.y + f2a.y + f3a.y) * dv + b.y;
    acc.z = (f0b.x + f1b.x + f2b.x + f3b.x) * dv + b.z;
    acc.w = (f0b.y + f1b.y + f2b.y + f3b.y) * dv + b.w;
    if (do_relu) {
        acc.x = fmaxf(acc.x, 0.f); acc.y = fmaxf(acc.y, 0.f);
        acc.z = fmaxf(acc.z, 0.f); acc.w = fmaxf(acc.w, 0.f);
    }
    uint2 u;
    u.x = h2u(__floats2half2_rn(acc.x, acc.y));
    u.y = h2u(__floats2half2_rn(acc.z, acc.w));
    g_act[(v << 5) + lane] = u;
}

// ---------------- mean pooling + classifier (fused); reads fp16 g_act ----------------
__device__ __forceinline__ int lower_bound_idx(const void* a, int val, int is64) {
    int lo = 0, hi = NN;
    while (lo < hi) {
        int mid = (lo + hi) >> 1;
        if (load_idx(a, mid, is64) < val) lo = mid + 1; else hi = mid;
    }
    return lo;
}

__global__ void __launch_bounds__(1024) k_pool(const void* __restrict__ batch,
                                               const float* __restrict__ Wc,
                                               const float* __restrict__ bc,
                                               float* __restrict__ out) {
    __shared__ int se[2];
    __shared__ float red[8][FF];
    __shared__ float pooled[FF];
    int g = blockIdx.x;
    if (threadIdx.x == 0) {
        int is64 = g_is64;
        se[0] = lower_bound_idx(batch, g, is64);
        se[1] = lower_bound_idx(batch, g + 1, is64);
    }
    __syncthreads();
    int s = se[0], e = se[1];
    int col = threadIdx.x & 127;
    int rc  = threadIdx.x >> 7;
    const __half* h = (const __half*)g_act;
    float sum = 0.f;
    for (int i = s + rc; i < e; i += 8) sum += __half2float(h[i * FF + col]);
    red[rc][col] = sum;
    __syncthreads();
    if (rc == 0) {
        float t = 0.f;
        #pragma unroll
        for (int k = 0; k < 8; k++) t += red[k][col];
        float cnt = (float)(e - s);
        pooled[col] = t / fmaxf(cnt, 1.0f);
    }
    __syncthreads();
    if (threadIdx.x < NC) {
        int c = threadIdx.x;
        float sumc = bc[c];
        #pragma unroll 8
        for (int k = 0; k < FF; k++)
            sumc += pooled[k] * Wc[k * NC + c];
        out[g * NC + c] = sumc;
    }
}

// ---------------- launch ----------------
extern "C" void kernel_launch(void* const* d_in, const int* in_sizes, int n_in,
                              void* d_out, int out_size) {
    const float* x  = (const float*)d_in[0];
    const void*  ei = d_in[1];
    const void*  batch = d_in[2];
    const float* W0 = (const float*)d_in[3];
    const float* b0 = (const float*)d_in[4];
    const float* W1 = (const float*)d_in[5];
    const float* b1 = (const float*)d_in[6];
    const float* W2 = (const float*)d_in[7];
    const float* b2 = (const float*)d_in[8];
    const float* Wc = (const float*)d_in[9];
    const float* bc = (const float*)d_in[10];
    float* out = (float*)d_out;

    static int attr_done = 0;
    if (!attr_done) {
        cudaFuncSetAttribute(k_gemm, cudaFuncAttributeMaxDynamicSharedMemorySize, GEMM_SMEM);
        attr_done = 1;
    }

    const int gemm_grid = (NN + BM - 1) / BM;        // 782
    const int agg_grid  = (NN + 7) / 8;

    k_init <<<(NN + 255) / 256, 256>>>((const int*)ei, W0, W1, W2);       // 1
    k_count<<<(NE + 255) / 256, 256>>>(ei);                               // 2
    k_scan <<<NBLK, SCAN_B>>>();                                          // 3
    k_gemm <<<gemm_grid + FILLB, 256, GEMM_SMEM>>>(x, 0, 0, ei, FILLB);   // 4 (gemm0 ∥ fill)
    k_agg  <<<agg_grid,  256>>>(b0, 1);                                   // 5
    k_gemm <<<gemm_grid, 256, GEMM_SMEM>>>(x, 1, 1, ei, 0);
    k_agg  <<<agg_grid,  256>>>(b1, 1);
    k_gemm <<<gemm_grid, 256, GEMM_SMEM>>>(x, 1, 2, ei, 0);
    k_agg  <<<agg_grid,  256>>>(b2, 0);

    k_pool<<<NG, 1024>>>(batch, Wc, bc, out);
}

// round 17
// speedup vs baseline: 2.1826x; 1.0419x over previous
#include <cuda_runtime.h>
#include <cuda_fp16.h>
#include <mma.h>

using namespace nvcuda;

#define NN 50000
#define NE 800000
#define FF 128
#define MQ 32                      // uint2 (4 halves) per fp16 row
#define NG 64
#define NC 16
#define SCAN_B 512
#define NBLK ((NN + SCAN_B - 1) / SCAN_B)   // 98
#define FILLB 200                  // fill-role blocks prepended to gemm0 grid
#define WCONV_B 64                 // W-conversion blocks in k_prep

// GEMM tiling (fp16 HMMA): BM=64 rows, full K=128 in one chunk, 8 warps.
#define BM 64
#define TSTR 136                   // smem row stride in halves (128 + 8 skew)
#define GEMM_SMEM 52224            // A 64*136*2 + W 128*136*2; Cs (64*136*4) reuses

// ---------------- scratch (static device globals; no allocation) ----------------
// INVARIANT: g_counts[] and g_sflag[] are all-zero at entry of every kernel_launch
// call (zero-initialized statics; re-zeroed each call by k_agg0 after k_scan).
__device__ int      g_is64;
__device__ int      g_counts[NN];
__device__ int      g_fill[NN];      // absolute write cursor
__device__ int      g_rowptr[NN + 1];
__device__ int      g_col[NE];
__device__ float    g_dinv[NN];
__device__ __half   g_Wh[3][FF * FF];  // fp16 weights (converted in k_prep)
__device__ uint2    g_msg[NN * MQ];    // fp16 messages (dinv-scaled GEMM output)
__device__ uint2    g_act[NN * MQ];    // fp16 activations (agg output, layer input)
__device__ volatile int g_sflag[NBLK]; // scan publish flags
__device__ volatile int g_sval[NBLK];  // scan block sums

// bit reinterpretation helpers
__device__ __forceinline__ unsigned h2u(__half2 h) { return *reinterpret_cast<unsigned*>(&h); }
__device__ __forceinline__ __half2 u2h(unsigned u) { return *reinterpret_cast<__half2*>(&u); }

// dtype-agnostic index load (edge_index / batch may be int32 or int64)
__device__ __forceinline__ int load_idx(const void* p, long long i, int is64) {
    if (is64) return (int)((const long long*)p)[i];
    return ((const int*)p)[i];
}

__device__ __forceinline__ int detect64(const int* __restrict__ w32) {
    int nz = 0;
    #pragma unroll
    for (int k = 0; k < 16; k++) nz |= w32[2 * k + 1];
    return (nz == 0) ? 1 : 0;
}

// ---------------- prep: W fp16 conversion + edge count (+ is64 publish) ----------------
// Blocks [0, WCONV_B): weight conversion. Blocks [WCONV_B, ...): degree histogram.
__global__ void k_prep(const int* __restrict__ w32,
                       const void* __restrict__ ei,
                       const float* __restrict__ W0,
                       const float* __restrict__ W1,
                       const float* __restrict__ W2) {
    if (blockIdx.x < WCONV_B) {
        int i = blockIdx.x * 256 + threadIdx.x;        // 0..16383
        if (i < FF * FF) {
            g_Wh[0][i] = __float2half_rn(W0[i]);
            g_Wh[1][i] = __float2half_rn(W1[i]);
            g_Wh[2][i] = __float2half_rn(W2[i]);
        }
        if (blockIdx.x == 0 && threadIdx.x == 0) g_is64 = detect64(w32);
        return;
    }
    __shared__ int s_is64;
    if (threadIdx.x == 0) s_is64 = detect64(w32);
    __syncthreads();
    long long i = (long long)(blockIdx.x - WCONV_B) * 256 + threadIdx.x;
    if (i < NE) {
        int d = load_idx(ei, (long long)NE + i, s_is64);
        atomicAdd(&g_counts[d], 1);
    }
}

// single-pass scan with decoupled lookback: rowptr, cursor, dinv in one kernel.
__global__ void __launch_bounds__(SCAN_B) k_scan() {
    __shared__ int warp_sums[SCAN_B / 32];
    __shared__ int s_off;
    int b = blockIdx.x;
    int i = b * SCAN_B + threadIdx.x;
    int v = (i < NN) ? g_counts[i] : 0;
    int lane = threadIdx.x & 31;
    int wid  = threadIdx.x >> 5;

    int x = v;
    #pragma unroll
    for (int off = 1; off < 32; off <<= 1) {
        int t = __shfl_up_sync(0xffffffffu, x, off);
        if (lane >= off) x += t;
    }
    if (lane == 31) warp_sums[wid] = x;
    __syncthreads();
    if (wid == 0) {
        int w = (lane < SCAN_B / 32) ? warp_sums[lane] : 0;
        #pragma unroll
        for (int off = 1; off < SCAN_B / 32; off <<= 1) {
            int t = __shfl_up_sync(0xffffffffu, w, off);
            if (lane >= off) w += t;
        }
        if (lane < SCAN_B / 32) warp_sums[lane] = w;
    }
    __syncthreads();
    int base = (wid > 0) ? warp_sums[wid - 1] : 0;
    int incl = base + x;

    if (threadIdx.x == SCAN_B - 1) {
        g_sval[b] = incl;
        __threadfence();
        g_sflag[b] = 1;
    }
    if (wid == 0) {
        int acc = 0;
        for (int k = lane; k < b; k += 32) {
            while (g_sflag[k] == 0) { }
            acc += g_sval[k];
        }
        #pragma unroll
        for (int off = 16; off; off >>= 1) acc += __shfl_down_sync(0xffffffffu, acc, off);
        if (lane == 0) s_off = acc;
    }
    __syncthreads();

    if (i < NN) {
        int rp = s_off + incl - v;
        g_rowptr[i] = rp;
        g_fill[i]   = rp;
        g_dinv[i]   = rsqrtf((float)(v + 1));
    }
    if (i == 0) g_rowptr[NN] = NE;
}

// ---------------- GEMM (fp16 HMMA) + optional fill role (fill blocks FIRST) ----------------
__global__ void __launch_bounds__(256) k_gemm(const float* __restrict__ xext,
                                              int srcSel,
                                              int wSel,
                                              const void* __restrict__ ei,
                                              int nFill) {
    extern __shared__ __align__(16) char smraw[];

    if (blockIdx.x < nFill) {
        // ---- fill role: scatter edges into CSR via absolute cursor ----
        int is64 = g_is64;
        for (long long i = (long long)blockIdx.x * blockDim.x + threadIdx.x; i < NE;
             i += (long long)nFill * blockDim.x) {
            int s = load_idx(ei, i, is64);
            int d = load_idx(ei, (long long)NE + i, is64);
            int pos = atomicAdd(&g_fill[d], 1);
            g_col[pos] = s;
        }
        return;
    }

    __half* As = (__half*)smraw;                  // 64 x TSTR
    __half* Ws = (__half*)smraw + BM * TSTR;      // 128 x TSTR
    float*  Cs = (float*)smraw;                   // 64 x TSTR floats (epilogue reuse)

    const bool useX = (srcSel == 0);
    const __half* Wh = g_Wh[wSel];
    int tid = threadIdx.x;
    int wid = tid >> 5;
    int stripe = wid >> 1;        // 0..3 -> rows [stripe*16, +16)
    int half_  = wid & 1;         // 0..1 -> cols [half_*64, +64)
    int rowBase = (blockIdx.x - nFill) * BM;

    // Load A: 64 rows x 128 halves = 64x32 quads, 8 per thread.
    #pragma unroll
    for (int t = 0; t < 8; t++) {
        int idx = tid + t * 256;
        int r   = idx >> 5;
        int q   = idx & 31;                       // quad of 4 halves
        int grow = rowBase + r;
        uint2 u = make_uint2(0u, 0u);
        if (grow < NN) {
            if (useX) {
                float4 v = *(const float4*)&xext[(long long)grow * FF + q * 4];
                u.x = h2u(__floats2half2_rn(v.x, v.y));
                u.y = h2u(__floats2half2_rn(v.z, v.w));
            } else {
                u = g_act[(grow << 5) + q];
            }
        }
        *(uint2*)&As[r * TSTR + q * 4] = u;
    }
    // Load W: 128 rows x 128 halves = 128x16 octs, 8 per thread.
    #pragma unroll
    for (int t = 0; t < 8; t++) {
        int idx = tid + t * 256;
        int k   = idx >> 4;
        int co  = idx & 15;                       // oct of 8 halves
        uint4 v = *(const uint4*)&Wh[k * FF + co * 8];
        *(uint4*)&Ws[k * TSTR + co * 8] = v;
    }
    __syncthreads();

    wmma::fragment<wmma::accumulator, 16, 16, 16, float> acc[4];
    #pragma unroll
    for (int c = 0; c < 4; c++) wmma::fill_fragment(acc[c], 0.0f);

    #pragma unroll
    for (int kk = 0; kk < 8; kk++) {              // K steps of 16
        wmma::fragment<wmma::matrix_a, 16, 16, 16, __half, wmma::row_major> a;
        wmma::load_matrix_sync(a, &As[(stripe * 16) * TSTR + kk * 16], TSTR);
        #pragma unroll
        for (int c = 0; c < 4; c++) {
            wmma::fragment<wmma::matrix_b, 16, 16, 16, __half, wmma::row_major> b;
            wmma::load_matrix_sync(b, &Ws[(kk * 16) * TSTR + half_ * 64 + c * 16], TSTR);
            wmma::mma_sync(acc[c], a, b, acc[c]);
        }
    }
    __syncthreads();

    // epilogue: frags -> Cs -> dinv scale -> fp16 -> global
    #pragma unroll
    for (int c = 0; c < 4; c++)
        wmma::store_matrix_sync(&Cs[(stripe * 16) * TSTR + half_ * 64 + c * 16],
                                acc[c], TSTR, wmma::mem_row_major);
    __syncthreads();

    #pragma unroll
    for (int t = 0; t < 8; t++) {
        int idx = tid + t * 256;                  // 64 rows x 32 quads
        int r = idx >> 5;
        int q = idx & 31;
        int grow = rowBase + r;
        if (grow < NN) {
            float dv = g_dinv[grow];
            float4 v = *(float4*)&Cs[r * TSTR + q * 4];
            uint2 u;
            u.x = h2u(__floats2half2_rn(v.x * dv, v.y * dv));
            u.y = h2u(__floats2half2_rn(v.z * dv, v.w * dv));
            g_msg[(grow << 5) + q] = u;
        }
    }
}

// ---------------- aggregation: act[v] = fp16( relu?( dinv[v]*sum msg + b ) ) ----
// zeroAux=1 (layer 0): also re-zero g_counts/g_sflag for the next call (invariant).
__global__ void __launch_bounds__(256) k_agg(const float* __restrict__ bias,
                                             int do_relu,
                                             int zeroAux) {
    int gtid = blockIdx.x * blockDim.x + threadIdx.x;
    if (zeroAux) {
        if (gtid < NN) g_counts[gtid] = 0;
        if (gtid < NBLK) g_sflag[gtid] = 0;
    }
    int v    = gtid >> 5;                          // one warp per node
    int lane = threadIdx.x & 31;
    if (v >= NN) return;

    uint2 mself = g_msg[(v << 5) + lane];
    __half2 c0a = u2h(mself.x), c0b = u2h(mself.y);
    __half2 z = __floats2half2_rn(0.f, 0.f);
    __half2 c1a = z, c1b = z, c2a = z, c2b = z, c3a = z, c3b = z;

    int s = g_rowptr[v];
    int deg = g_rowptr[v + 1] - s;

    for (int base = 0; base < deg; base += 32) {
        int rem = deg - base;
        int n = rem < 32 ? rem : 32;
        int myc = 0;
        if (lane < n) myc = g_col[s + base + lane];            // coalesced prefetch

        int jj = 0;
        for (; jj + 8 <= n; jj += 8) {
            int u0 = __shfl_sync(0xffffffffu, myc, jj);
            int u1 = __shfl_sync(0xffffffffu, myc, jj + 1);
            int u2 = __shfl_sync(0xffffffffu, myc, jj + 2);
            int u3 = __shfl_sync(0xffffffffu, myc, jj + 3);
            int u4 = __shfl_sync(0xffffffffu, myc, jj + 4);
            int u5 = __shfl_sync(0xffffffffu, myc, jj + 5);
            int u6 = __shfl_sync(0xffffffffu, myc, jj + 6);
            int u7 = __shfl_sync(0xffffffffu, myc, jj + 7);
            uint2 m0 = g_msg[(u0 << 5) + lane];
            uint2 m1 = g_msg[(u1 << 5) + lane];
            uint2 m2 = g_msg[(u2 << 5) + lane];
            uint2 m3 = g_msg[(u3 << 5) + lane];
            uint2 m4 = g_msg[(u4 << 5) + lane];
            uint2 m5 = g_msg[(u5 << 5) + lane];
            uint2 m6 = g_msg[(u6 << 5) + lane];
            uint2 m7 = g_msg[(u7 << 5) + lane];
            c0a = __hadd2(c0a, u2h(m0.x)); c0b = __hadd2(c0b, u2h(m0.y));
            c1a = __hadd2(c1a, u2h(m1.x)); c1b = __hadd2(c1b, u2h(m1.y));
            c2a = __hadd2(c2a, u2h(m2.x)); c2b = __hadd2(c2b, u2h(m2.y));
            c3a = __hadd2(c3a, u2h(m3.x)); c3b = __hadd2(c3b, u2h(m3.y));
            c0a = __hadd2(c0a, u2h(m4.x)); c0b = __hadd2(c0b, u2h(m4.y));
            c1a = __hadd2(c1a, u2h(m5.x)); c1b = __hadd2(c1b, u2h(m5.y));
            c2a = __hadd2(c2a, u2h(m6.x)); c2b = __hadd2(c2b, u2h(m6.y));
            c3a = __hadd2(c3a, u2h(m7.x)); c3b = __hadd2(c3b, u2h(m7.y));
        }
        for (; jj + 2 <= n; jj += 2) {
            int u0 = __shfl_sync(0xffffffffu, myc, jj);
            int u1 = __shfl_sync(0xffffffffu, myc, jj + 1);
            uint2 m0 = g_msg[(u0 << 5) + lane];
            uint2 m1 = g_msg[(u1 << 5) + lane];
            c0a = __hadd2(c0a, u2h(m0.x)); c0b = __hadd2(c0b, u2h(m0.y));
            c1a = __hadd2(c1a, u2h(m1.x)); c1b = __hadd2(c1b, u2h(m1.y));
        }
        if (jj < n) {
            int u = __shfl_sync(0xffffffffu, myc, jj);
            uint2 m = g_msg[(u << 5) + lane];
            c2a = __hadd2(c2a, u2h(m.x)); c2b = __hadd2(c2b, u2h(m.y));
        }
    }

    float2 f0a = __half22float2(c0a), f1a = __half22float2(c1a);
    float2 f2a = __half22float2(c2a), f3a = __half22float2(c3a);
    float2 f0b = __half22float2(c0b), f1b = __half22float2(c1b);
    float2 f2b = __half22float2(c2b), f3b = __half22float2(c3b);

    float  dv = g_dinv[v];
    float4 b  = *(const float4*)&bias[lane * 4];
    float4 acc;
    acc.x = (f0a.x + f1a.x + f2a.x + f3a.x) * dv + b.x;
    acc.y = (f0a.y + f1a.y + f2a.y + f3a.y) * dv + b.y;
    acc.z = (f0b.x + f1b.x + f2b.x + f3b.x) * dv + b.z;
    acc.w = (f0b.y + f1b.y + f2b.y + f3b.y) * dv + b.w;
    if (do_relu) {
        acc.x = fmaxf(acc.x, 0.f); acc.y = fmaxf(acc.y, 0.f);
        acc.z = fmaxf(acc.z, 0.f); acc.w = fmaxf(acc.w, 0.f);
    }
    uint2 u;
    u.x = h2u(__floats2half2_rn(acc.x, acc.y));
    u.y = h2u(__floats2half2_rn(acc.z, acc.w));
    g_act[(v << 5) + lane] = u;
}

// ---------------- mean pooling + classifier (fused); reads fp16 g_act ----------------
__device__ __forceinline__ int lower_bound_idx(const void* a, int val, int is64) {
    int lo = 0, hi = NN;
    while (lo < hi) {
        int mid = (lo + hi) >> 1;
        if (load_idx(a, mid, is64) < val) lo = mid + 1; else hi = mid;
    }
    return lo;
}

__global__ void __launch_bounds__(1024) k_pool(const void* __restrict__ batch,
                                               const float* __restrict__ Wc,
                                               const float* __restrict__ bc,
                                               float* __restrict__ out) {
    __shared__ int se[2];
    __shared__ float red[8][FF];
    __shared__ float pooled[FF];
    int g = blockIdx.x;
    if (threadIdx.x == 0) {
        int is64 = g_is64;
        se[0] = lower_bound_idx(batch, g, is64);
        se[1] = lower_bound_idx(batch, g + 1, is64);
    }
    __syncthreads();
    int s = se[0], e = se[1];
    int col = threadIdx.x & 127;
    int rc  = threadIdx.x >> 7;
    const __half* h = (const __half*)g_act;
    float sum = 0.f;
    for (int i = s + rc; i < e; i += 8) sum += __half2float(h[i * FF + col]);
    red[rc][col] = sum;
    __syncthreads();
    if (rc == 0) {
        float t = 0.f;
        #pragma unroll
        for (int k = 0; k < 8; k++) t += red[k][col];
        float cnt = (float)(e - s);
        pooled[col] = t / fmaxf(cnt, 1.0f);
    }
    __syncthreads();
    if (threadIdx.x < NC) {
        int c = threadIdx.x;
        float sumc = bc[c];
        #pragma unroll 8
        for (int k = 0; k < FF; k++)
            sumc += pooled[k] * Wc[k * NC + c];
        out[g * NC + c] = sumc;
    }
}

// ---------------- launch ----------------
extern "C" void kernel_launch(void* const* d_in, const int* in_sizes, int n_in,
                              void* d_out, int out_size) {
    const float* x  = (const float*)d_in[0];
    const void*  ei = d_in[1];
    const void*  batch = d_in[2];
    const float* W0 = (const float*)d_in[3];
    const float* b0 = (const float*)d_in[4];
    const float* W1 = (const float*)d_in[5];
    const float* b1 = (const float*)d_in[6];
    const float* W2 = (const float*)d_in[7];
    const float* b2 = (const float*)d_in[8];
    const float* Wc = (const float*)d_in[9];
    const float* bc = (const float*)d_in[10];
    float* out = (float*)d_out;

    static int attr_done = 0;
    if (!attr_done) {
        cudaFuncSetAttribute(k_gemm, cudaFuncAttributeMaxDynamicSharedMemorySize, GEMM_SMEM);
        attr_done = 1;
    }

    const int gemm_grid = (NN + BM - 1) / BM;        // 782
    const int agg_grid  = (NN + 7) / 8;
    const int prep_grid = WCONV_B + (NE + 255) / 256;

    k_prep <<<prep_grid, 256>>>((const int*)ei, ei, W0, W1, W2);          // 1
    k_scan <<<NBLK, SCAN_B>>>();                                          // 2
    k_gemm <<<FILLB + gemm_grid, 256, GEMM_SMEM>>>(x, 0, 0, ei, FILLB);   // 3 (fill ∥ gemm0)
    k_agg  <<<agg_grid,  256>>>(b0, 1, 1);                                // 4 (+aux re-zero)
    k_gemm <<<gemm_grid, 256, GEMM_SMEM>>>(x, 1, 1, ei, 0);
    k_agg  <<<agg_grid,  256>>>(b1, 1, 0);
    k_gemm <<<gemm_grid, 256, GEMM_SMEM>>>(x, 1, 2, ei, 0);
    k_agg  <<<agg_grid,  256>>>(b2, 0, 0);

    k_pool<<<NG, 1024>>>(batch, Wc, bc, out);
}